// round 1
// baseline (speedup 1.0000x reference)
#include <cuda_runtime.h>
#include <math.h>

// Problem constants
#define TOK 100352              // B * H * W = 32*56*56
#define SCALE 0.17677669529663687f  // 32^-0.5

// Scratch (alloc-free rule: __device__ globals)
__device__ float g_x[19267584];       // (B, H*W, C) running activation
__device__ float g_hwin[19267584];    // windowed LN1 output (win*49+tok, 192)
__device__ float g_q[19267584];       // (2048,6,49,32)
__device__ float g_k[19267584];
__device__ float g_v[19267584];
__device__ float g_attnout[19267584]; // (win*49+tok, 192)
__device__ float g_ln2[19267584];
__device__ float g_hid[77070336];     // (100352, 768)

__device__ __forceinline__ float warp_sum(float v) {
#pragma unroll
    for (int o = 16; o; o >>= 1) v += __shfl_xor_sync(0xffffffffu, v, o);
    return v;
}

__global__ void copy_in_kernel(const float* __restrict__ src) {
    size_t i = (size_t)blockIdx.x * blockDim.x + threadIdx.x;
    ((float4*)g_x)[i] = ((const float4*)src)[i];
}

__global__ void copy_out_kernel(float* __restrict__ dst) {
    size_t i = (size_t)blockIdx.x * blockDim.x + threadIdx.x;
    ((float4*)dst)[i] = ((const float4*)g_x)[i];
}

// LN1 + cyclic shift + window partition. One warp per OUTPUT (windowed) token.
__global__ void ln1_part_kernel(const float* __restrict__ w, const float* __restrict__ b, int shift) {
    int gw = (blockIdx.x * blockDim.x + threadIdx.x) >> 5;
    int lane = threadIdx.x & 31;
    if (gw >= TOK) return;
    int win = gw / 49, tok = gw % 49;
    int bb = win >> 6, w64 = win & 63;
    int wh = w64 >> 3, wwi = w64 & 7;
    int ii = tok / 7, jj = tok % 7;
    int sh = (wh * 7 + ii + shift) % 56;
    int sw = (wwi * 7 + jj + shift) % 56;
    const float* src = g_x + ((size_t)bb * 3136 + sh * 56 + sw) * 192;
    float v[6];
    float s = 0.f;
#pragma unroll
    for (int q = 0; q < 6; q++) { v[q] = src[lane + q * 32]; s += v[q]; }
    s = warp_sum(s);
    float mean = s * (1.f / 192.f);
    float ss = 0.f;
#pragma unroll
    for (int q = 0; q < 6; q++) { float d = v[q] - mean; ss += d * d; }
    ss = warp_sum(ss);
    float rstd = rsqrtf(ss * (1.f / 192.f) + 1e-5f);
    float* dst = g_hwin + (size_t)gw * 192;
#pragma unroll
    for (int q = 0; q < 6; q++) {
        int c = lane + q * 32;
        dst[c] = (v[q] - mean) * rstd * w[c] + b[c];
    }
}

// LN2: plain per-token LN, g_x -> g_ln2
__global__ void ln2_kernel(const float* __restrict__ w, const float* __restrict__ b) {
    int gw = (blockIdx.x * blockDim.x + threadIdx.x) >> 5;
    int lane = threadIdx.x & 31;
    if (gw >= TOK) return;
    const float* src = g_x + (size_t)gw * 192;
    float v[6];
    float s = 0.f;
#pragma unroll
    for (int q = 0; q < 6; q++) { v[q] = src[lane + q * 32]; s += v[q]; }
    s = warp_sum(s);
    float mean = s * (1.f / 192.f);
    float ss = 0.f;
#pragma unroll
    for (int q = 0; q < 6; q++) { float d = v[q] - mean; ss += d * d; }
    ss = warp_sum(ss);
    float rstd = rsqrtf(ss * (1.f / 192.f) + 1e-5f);
    float* dst = g_ln2 + (size_t)gw * 192;
#pragma unroll
    for (int q = 0; q < 6; q++) {
        int c = lane + q * 32;
        dst[c] = (v[q] - mean) * rstd * w[c] + b[c];
    }
}

__device__ __forceinline__ int reg3(int h) { return h < 49 ? 0 : (h < 53 ? 1 : 2); }

// One block per (window, head). q/k/v in (2048,6,49,32) layout.
__global__ void __launch_bounds__(256) attn_kernel(const float* __restrict__ rpb, int shift) {
    __shared__ float qs[1568];   // [i][d]
    __shared__ float ks[1568];   // transposed: [d][j] with stride 49
    __shared__ float vs[1568];   // [j][d]
    __shared__ float S[2401];    // [i][j]
    int bid = blockIdx.x;        // win*6 + head
    int win = bid / 6, head = bid % 6;
    int tid = threadIdx.x;
    const float* qg = g_q + (size_t)bid * 1568;
    const float* kg = g_k + (size_t)bid * 1568;
    const float* vg = g_v + (size_t)bid * 1568;
    for (int idx = tid; idx < 1568; idx += 256) {
        qs[idx] = qg[idx];
        int j = idx >> 5, dd = idx & 31;
        ks[dd * 49 + j] = kg[idx];
        vs[idx] = vg[idx];
    }
    __syncthreads();
    int w64 = win & 63, wh = w64 >> 3, wwi = w64 & 7;
    for (int e = tid; e < 2401; e += 256) {
        int i = e / 49, j = e % 49;
        float s = 0.f;
#pragma unroll
        for (int d = 0; d < 32; d++) s += qs[i * 32 + d] * ks[d * 49 + j];
        int yi = i / 7, xi = i % 7, yj = j / 7, xj = j % 7;
        int ridx = (yi - yj + 6) * 13 + (xi - xj + 6);
        s += rpb[ridx * 6 + head];
        if (shift) {
            int ri = reg3(wh * 7 + yi) * 3 + reg3(wwi * 7 + xi);
            int rj = reg3(wh * 7 + yj) * 3 + reg3(wwi * 7 + xj);
            if (ri != rj) s -= 100.0f;
        }
        S[e] = s;
    }
    __syncthreads();
    if (tid < 49) {
        float* row = S + tid * 49;
        float mx = -1e30f;
        for (int j = 0; j < 49; j++) mx = fmaxf(mx, row[j]);
        float sum = 0.f;
        for (int j = 0; j < 49; j++) { float e = expf(row[j] - mx); row[j] = e; sum += e; }
        float inv = 1.f / sum;
        for (int j = 0; j < 49; j++) row[j] *= inv;
    }
    __syncthreads();
    for (int e = tid; e < 1568; e += 256) {
        int i = e >> 5, d = e & 31;
        float o = 0.f;
#pragma unroll
        for (int j = 0; j < 49; j++) o += S[i * 49 + j] * vs[j * 32 + d];
        g_attnout[((size_t)(win * 49 + i)) * 192 + head * 32 + d] = o;
    }
}

// 64x64 fp32 GEMM: out[m,n] = A[m,:] . W[n,:] + bias[n], with mode-specific epilogue.
// MODE 0: A=g_hwin, write q(*SCALE)/k/v in (win,head,tok,d) layout
// MODE 1: A=g_attnout, scatter (window-reverse + roll-back) residual add into g_x
// MODE 2: A=g_ln2, GELU -> g_hid (stride 768)
// MODE 3: A=g_hid, residual add into g_x (stride 192)
template <int MODE>
__global__ void __launch_bounds__(256) gemm64(const float* __restrict__ W,
                                              const float* __restrict__ bias,
                                              int K, int shift) {
    __shared__ float As[16 * 68];
    __shared__ float Bs[16 * 68];
    const float* A = (MODE == 0) ? g_hwin : (MODE == 1) ? g_attnout : (MODE == 2) ? g_ln2 : g_hid;
    int bm = blockIdx.x * 64;
    int bn = blockIdx.y * 64;
    int tid = threadIdx.x;
    int tx = tid & 15, ty = tid >> 4;
    int lr = tid >> 2;           // row 0..63 of the tile being loaded
    int lc = (tid & 3) << 2;     // k offset 0,4,8,12
    float acc[4][4] = {};
    const float* Aptr = A + (size_t)(bm + lr) * K + lc;
    const float* Wptr = W + (size_t)(bn + lr) * K + lc;
    for (int k0 = 0; k0 < K; k0 += 16) {
        float4 av = *(const float4*)(Aptr + k0);
        float4 wv = *(const float4*)(Wptr + k0);
        As[(lc + 0) * 68 + lr] = av.x;
        As[(lc + 1) * 68 + lr] = av.y;
        As[(lc + 2) * 68 + lr] = av.z;
        As[(lc + 3) * 68 + lr] = av.w;
        Bs[(lc + 0) * 68 + lr] = wv.x;
        Bs[(lc + 1) * 68 + lr] = wv.y;
        Bs[(lc + 2) * 68 + lr] = wv.z;
        Bs[(lc + 3) * 68 + lr] = wv.w;
        __syncthreads();
#pragma unroll
        for (int kk = 0; kk < 16; kk++) {
            float4 a = *(const float4*)&As[kk * 68 + tx * 4];
            float4 b = *(const float4*)&Bs[kk * 68 + ty * 4];
            acc[0][0] += a.x * b.x; acc[0][1] += a.x * b.y; acc[0][2] += a.x * b.z; acc[0][3] += a.x * b.w;
            acc[1][0] += a.y * b.x; acc[1][1] += a.y * b.y; acc[1][2] += a.y * b.z; acc[1][3] += a.y * b.w;
            acc[2][0] += a.z * b.x; acc[2][1] += a.z * b.y; acc[2][2] += a.z * b.z; acc[2][3] += a.z * b.w;
            acc[3][0] += a.w * b.x; acc[3][1] += a.w * b.y; acc[3][2] += a.w * b.z; acc[3][3] += a.w * b.w;
        }
        __syncthreads();
    }
#pragma unroll
    for (int i2 = 0; i2 < 4; i2++) {
        int m = bm + tx * 4 + i2;
#pragma unroll
        for (int j2 = 0; j2 < 4; j2++) {
            int n = bn + ty * 4 + j2;
            float val = acc[i2][j2] + bias[n];
            if (MODE == 0) {
                int part = n / 192, rem = n % 192, head = rem >> 5, dd = rem & 31;
                int win = m / 49, tok = m % 49;
                size_t dst = ((size_t)(win * 6 + head) * 49 + tok) * 32 + dd;
                if (part == 0) g_q[dst] = val * SCALE;
                else if (part == 1) g_k[dst] = val;
                else g_v[dst] = val;
            } else if (MODE == 1) {
                int win = m / 49, tok = m % 49;
                int bb = win >> 6, w64 = win & 63, wh = w64 >> 3, wwi = w64 & 7;
                int ii = tok / 7, jj = tok % 7;
                int hh = wh * 7 + ii, gc = wwi * 7 + jj;
                if (shift) { hh = (hh + 7) % 56; gc = (gc + 7) % 56; }
                size_t dst = ((size_t)bb * 3136 + hh * 56 + gc) * 192 + n;
                g_x[dst] += val;
            } else if (MODE == 2) {
                g_hid[(size_t)m * 768 + n] = val * 0.5f * (1.f + erff(val * 0.70710678118654752f));
            } else {
                g_x[(size_t)m * 192 + n] += val;
            }
        }
    }
}

extern "C" void kernel_launch(void* const* d_in, const int* in_sizes, int n_in,
                              void* d_out, int out_size) {
    const float* x     = (const float*)d_in[0];
    const float* n1w   = (const float*)d_in[1];
    const float* n1b   = (const float*)d_in[2];
    const float* qkvw  = (const float*)d_in[3];
    const float* qkvb  = (const float*)d_in[4];
    const float* rpb   = (const float*)d_in[5];
    const float* projw = (const float*)d_in[6];
    const float* projb = (const float*)d_in[7];
    const float* n2w   = (const float*)d_in[8];
    const float* n2b   = (const float*)d_in[9];
    const float* f1w   = (const float*)d_in[10];
    const float* f1b   = (const float*)d_in[11];
    const float* f2w   = (const float*)d_in[12];
    const float* f2b   = (const float*)d_in[13];

    copy_in_kernel<<<18816, 256>>>(x);
    for (int d = 0; d < 2; d++) {
        int shift = d ? 3 : 0;
        ln1_part_kernel<<<12544, 256>>>(n1w + d * 192, n1b + d * 192, shift);
        gemm64<0><<<dim3(1568, 9), 256>>>(qkvw + (size_t)d * 576 * 192, qkvb + d * 576, 192, 0);
        attn_kernel<<<12288, 256>>>(rpb + d * 169 * 6, shift);
        gemm64<1><<<dim3(1568, 3), 256>>>(projw + (size_t)d * 192 * 192, projb + d * 192, 192, shift);
        ln2_kernel<<<12544, 256>>>(n2w + d * 192, n2b + d * 192);
        gemm64<2><<<dim3(1568, 12), 256>>>(f1w + (size_t)d * 768 * 192, f1b + d * 768, 192, 0);
        gemm64<3><<<dim3(1568, 3), 256>>>(f2w + (size_t)d * 192 * 768, f2b + d * 192, 768, 0);
    }
    copy_out_kernel<<<18816, 256>>>((float*)d_out);
}

// round 5
// speedup vs baseline: 1.3157x; 1.3157x over previous
#include <cuda_runtime.h>
#include <math.h>

#define TOK 100352
#define SCALE 0.17677669529663687f

__device__ float g_x[19267584];
__device__ float g_hwin[19267584];
__device__ float g_q[19267584];
__device__ float g_k[19267584];
__device__ float g_v[19267584];
__device__ float g_attnout[19267584];
__device__ float g_ln2[19267584];
__device__ float g_hid[77070336];

__device__ __forceinline__ float warp_sum(float v) {
#pragma unroll
    for (int o = 16; o; o >>= 1) v += __shfl_xor_sync(0xffffffffu, v, o);
    return v;
}

__device__ __forceinline__ unsigned f2tf32(float f) {
    unsigned r;
    asm("cvt.rna.tf32.f32 %0, %1;" : "=r"(r) : "f"(f));
    return r;
}

__global__ void copy_in_kernel(const float* __restrict__ src) {
    size_t i = (size_t)blockIdx.x * blockDim.x + threadIdx.x;
    ((float4*)g_x)[i] = ((const float4*)src)[i];
}

__global__ void copy_out_kernel(float* __restrict__ dst) {
    size_t i = (size_t)blockIdx.x * blockDim.x + threadIdx.x;
    ((float4*)dst)[i] = ((const float4*)g_x)[i];
}

__global__ void ln1_part_kernel(const float* __restrict__ w, const float* __restrict__ b, int shift) {
    int gw = (blockIdx.x * blockDim.x + threadIdx.x) >> 5;
    int lane = threadIdx.x & 31;
    if (gw >= TOK) return;
    int win = gw / 49, tok = gw % 49;
    int bb = win >> 6, w64 = win & 63;
    int wh = w64 >> 3, wwi = w64 & 7;
    int ii = tok / 7, jj = tok % 7;
    int sh = (wh * 7 + ii + shift) % 56;
    int sw = (wwi * 7 + jj + shift) % 56;
    const float* src = g_x + ((size_t)bb * 3136 + sh * 56 + sw) * 192;
    float v[6];
    float s = 0.f;
#pragma unroll
    for (int q = 0; q < 6; q++) { v[q] = src[lane + q * 32]; s += v[q]; }
    s = warp_sum(s);
    float mean = s * (1.f / 192.f);
    float ss = 0.f;
#pragma unroll
    for (int q = 0; q < 6; q++) { float d = v[q] - mean; ss += d * d; }
    ss = warp_sum(ss);
    float rstd = rsqrtf(ss * (1.f / 192.f) + 1e-5f);
    float* dst = g_hwin + (size_t)gw * 192;
#pragma unroll
    for (int q = 0; q < 6; q++) {
        int c = lane + q * 32;
        dst[c] = (v[q] - mean) * rstd * w[c] + b[c];
    }
}

__global__ void ln2_kernel(const float* __restrict__ w, const float* __restrict__ b) {
    int gw = (blockIdx.x * blockDim.x + threadIdx.x) >> 5;
    int lane = threadIdx.x & 31;
    if (gw >= TOK) return;
    const float* src = g_x + (size_t)gw * 192;
    float v[6];
    float s = 0.f;
#pragma unroll
    for (int q = 0; q < 6; q++) { v[q] = src[lane + q * 32]; s += v[q]; }
    s = warp_sum(s);
    float mean = s * (1.f / 192.f);
    float ss = 0.f;
#pragma unroll
    for (int q = 0; q < 6; q++) { float d = v[q] - mean; ss += d * d; }
    ss = warp_sum(ss);
    float rstd = rsqrtf(ss * (1.f / 192.f) + 1e-5f);
    float* dst = g_ln2 + (size_t)gw * 192;
#pragma unroll
    for (int q = 0; q < 6; q++) {
        int c = lane + q * 32;
        dst[c] = (v[q] - mean) * rstd * w[c] + b[c];
    }
}

__device__ __forceinline__ int reg3(int h) { return h < 49 ? 0 : (h < 53 ? 1 : 2); }

__global__ void __launch_bounds__(256) attn_kernel(const float* __restrict__ rpb, int shift) {
    __shared__ float qs[1568];
    __shared__ float ks[1568];
    __shared__ float vs[1568];
    __shared__ float S[2401];
    int bid = blockIdx.x;
    int win = bid / 6, head = bid % 6;
    int tid = threadIdx.x;
    const float* qg = g_q + (size_t)bid * 1568;
    const float* kg = g_k + (size_t)bid * 1568;
    const float* vg = g_v + (size_t)bid * 1568;
    for (int idx = tid; idx < 1568; idx += 256) {
        qs[idx] = qg[idx];
        int j = idx >> 5, dd = idx & 31;
        ks[dd * 49 + j] = kg[idx];
        vs[idx] = vg[idx];
    }
    __syncthreads();
    int w64 = win & 63, wh = w64 >> 3, wwi = w64 & 7;
    for (int e = tid; e < 2401; e += 256) {
        int i = e / 49, j = e % 49;
        float s = 0.f;
#pragma unroll
        for (int d = 0; d < 32; d++) s += qs[i * 32 + d] * ks[d * 49 + j];
        int yi = i / 7, xi = i % 7, yj = j / 7, xj = j % 7;
        int ridx = (yi - yj + 6) * 13 + (xi - xj + 6);
        s += rpb[ridx * 6 + head];
        if (shift) {
            int ri = reg3(wh * 7 + yi) * 3 + reg3(wwi * 7 + xi);
            int rj = reg3(wh * 7 + yj) * 3 + reg3(wwi * 7 + xj);
            if (ri != rj) s -= 100.0f;
        }
        S[e] = s;
    }
    __syncthreads();
    if (tid < 49) {
        float* row = S + tid * 49;
        float mx = -1e30f;
        for (int j = 0; j < 49; j++) mx = fmaxf(mx, row[j]);
        float sum = 0.f;
        for (int j = 0; j < 49; j++) { float e = expf(row[j] - mx); row[j] = e; sum += e; }
        float inv = 1.f / sum;
        for (int j = 0; j < 49; j++) row[j] *= inv;
    }
    __syncthreads();
    for (int e = tid; e < 1568; e += 256) {
        int i = e >> 5, d = e & 31;
        float o = 0.f;
#pragma unroll
        for (int j = 0; j < 49; j++) o += S[i * 49 + j] * vs[j * 32 + d];
        g_attnout[((size_t)(win * 49 + i)) * 192 + head * 32 + d] = o;
    }
}

// ---------------- tf32 tensor-core GEMM, 128x64 tile, BK=16 ----------------
// out[m,n] = A[m,:] . W[n,:] + bias[n]; epilogue per MODE (same as before).
#define ASTRIDE 132
#define BSTRIDE 68

template <int MODE>
__global__ void __launch_bounds__(256) gemm_tc(const float* __restrict__ W,
                                               const float* __restrict__ bias,
                                               int K, int shift) {
    __shared__ unsigned As[2][16 * ASTRIDE];
    __shared__ unsigned Bs[2][16 * BSTRIDE];
    const float* A = (MODE == 0) ? g_hwin : (MODE == 1) ? g_attnout : (MODE == 2) ? g_ln2 : g_hid;
    const int bm = blockIdx.x * 128;
    const int bn = blockIdx.y * 64;
    const int tid = threadIdx.x;
    const int warp = tid >> 5, lane = tid & 31;
    const int wm = warp >> 1, wn = warp & 1;         // 4 x 2 warps
    const int g = lane >> 2, tg = lane & 3;

    // gmem staging assignments
    const int am0 = tid & 127, akq0 = (tid >> 7) * 4;          // l=0
    const int am1 = (tid + 256) & 127, akq1 = ((tid + 256) >> 7) * 4;  // l=1
    const int bn0 = tid & 63, bkq0 = (tid >> 6) * 4;

    const float* Arow0 = A + (size_t)(bm + am0) * K + akq0;
    const float* Arow1 = A + (size_t)(bm + am1) * K + akq1;
    const float* Wrow = W + (size_t)(bn + bn0) * K + bkq0;

    float acc[2][4][4];
#pragma unroll
    for (int i = 0; i < 2; i++)
#pragma unroll
        for (int j = 0; j < 4; j++)
#pragma unroll
            for (int r = 0; r < 4; r++) acc[i][j][r] = 0.f;

    const int steps = K >> 4;
    float4 ra0 = *(const float4*)Arow0;
    float4 ra1 = *(const float4*)Arow1;
    float4 rb0 = *(const float4*)Wrow;
    {
        unsigned* a = As[0];
        a[(akq0 + 0) * ASTRIDE + am0] = f2tf32(ra0.x);
        a[(akq0 + 1) * ASTRIDE + am0] = f2tf32(ra0.y);
        a[(akq0 + 2) * ASTRIDE + am0] = f2tf32(ra0.z);
        a[(akq0 + 3) * ASTRIDE + am0] = f2tf32(ra0.w);
        a[(akq1 + 0) * ASTRIDE + am1] = f2tf32(ra1.x);
        a[(akq1 + 1) * ASTRIDE + am1] = f2tf32(ra1.y);
        a[(akq1 + 2) * ASTRIDE + am1] = f2tf32(ra1.z);
        a[(akq1 + 3) * ASTRIDE + am1] = f2tf32(ra1.w);
        unsigned* bptr = Bs[0];
        bptr[(bkq0 + 0) * BSTRIDE + bn0] = f2tf32(rb0.x);
        bptr[(bkq0 + 1) * BSTRIDE + bn0] = f2tf32(rb0.y);
        bptr[(bkq0 + 2) * BSTRIDE + bn0] = f2tf32(rb0.z);
        bptr[(bkq0 + 3) * BSTRIDE + bn0] = f2tf32(rb0.w);
    }
    __syncthreads();

    for (int it = 0; it < steps; it++) {
        const int cur = it & 1;
        const bool more = (it + 1) < steps;
        if (more) {
            int ko = (it + 1) << 4;
            ra0 = *(const float4*)(Arow0 + ko);
            ra1 = *(const float4*)(Arow1 + ko);
            rb0 = *(const float4*)(Wrow + ko);
        }
        const unsigned* as = As[cur];
        const unsigned* bs = Bs[cur];
#pragma unroll
        for (int kk = 0; kk < 2; kk++) {
            unsigned af[2][4], bf[4][2];
            const int k0 = kk * 8 + tg;
#pragma unroll
            for (int mt = 0; mt < 2; mt++) {
                int rb = wm * 32 + mt * 16 + g;
                af[mt][0] = as[k0 * ASTRIDE + rb];
                af[mt][1] = as[k0 * ASTRIDE + rb + 8];
                af[mt][2] = as[(k0 + 4) * ASTRIDE + rb];
                af[mt][3] = as[(k0 + 4) * ASTRIDE + rb + 8];
            }
#pragma unroll
            for (int nt = 0; nt < 4; nt++) {
                int nb = wn * 32 + nt * 8 + g;
                bf[nt][0] = bs[k0 * BSTRIDE + nb];
                bf[nt][1] = bs[(k0 + 4) * BSTRIDE + nb];
            }
#pragma unroll
            for (int mt = 0; mt < 2; mt++)
#pragma unroll
                for (int nt = 0; nt < 4; nt++) {
                    asm volatile(
                        "mma.sync.aligned.m16n8k8.row.col.f32.tf32.tf32.f32 "
                        "{%0,%1,%2,%3}, {%4,%5,%6,%7}, {%8,%9}, {%0,%1,%2,%3};\n"
                        : "+f"(acc[mt][nt][0]), "+f"(acc[mt][nt][1]),
                          "+f"(acc[mt][nt][2]), "+f"(acc[mt][nt][3])
                        : "r"(af[mt][0]), "r"(af[mt][1]), "r"(af[mt][2]), "r"(af[mt][3]),
                          "r"(bf[nt][0]), "r"(bf[nt][1]));
                }
        }
        if (more) {
            unsigned* a = As[cur ^ 1];
            a[(akq0 + 0) * ASTRIDE + am0] = f2tf32(ra0.x);
            a[(akq0 + 1) * ASTRIDE + am0] = f2tf32(ra0.y);
            a[(akq0 + 2) * ASTRIDE + am0] = f2tf32(ra0.z);
            a[(akq0 + 3) * ASTRIDE + am0] = f2tf32(ra0.w);
            a[(akq1 + 0) * ASTRIDE + am1] = f2tf32(ra1.x);
            a[(akq1 + 1) * ASTRIDE + am1] = f2tf32(ra1.y);
            a[(akq1 + 2) * ASTRIDE + am1] = f2tf32(ra1.z);
            a[(akq1 + 3) * ASTRIDE + am1] = f2tf32(ra1.w);
            unsigned* bp = Bs[cur ^ 1];
            bp[(bkq0 + 0) * BSTRIDE + bn0] = f2tf32(rb0.x);
            bp[(bkq0 + 1) * BSTRIDE + bn0] = f2tf32(rb0.y);
            bp[(bkq0 + 2) * BSTRIDE + bn0] = f2tf32(rb0.z);
            bp[(bkq0 + 3) * BSTRIDE + bn0] = f2tf32(rb0.w);
            __syncthreads();
        }
    }

#pragma unroll
    for (int mt = 0; mt < 2; mt++)
#pragma unroll
        for (int nt = 0; nt < 4; nt++)
#pragma unroll
            for (int r = 0; r < 4; r++) {
                int m = bm + wm * 32 + mt * 16 + g + ((r >= 2) ? 8 : 0);
                int n = bn + wn * 32 + nt * 8 + tg * 2 + (r & 1);
                float val = acc[mt][nt][r] + bias[n];
                if (MODE == 0) {
                    int part = n / 192, rem = n % 192, head = rem >> 5, dd = rem & 31;
                    int win = m / 49, tok = m % 49;
                    size_t dst = ((size_t)(win * 6 + head) * 49 + tok) * 32 + dd;
                    if (part == 0) g_q[dst] = val * SCALE;
                    else if (part == 1) g_k[dst] = val;
                    else g_v[dst] = val;
                } else if (MODE == 1) {
                    int win = m / 49, tok = m % 49;
                    int bb = win >> 6, w64 = win & 63, wh = w64 >> 3, wwi = w64 & 7;
                    int ii = tok / 7, jj = tok % 7;
                    int hh = wh * 7 + ii, gc = wwi * 7 + jj;
                    if (shift) { hh = (hh + 7) % 56; gc = (gc + 7) % 56; }
                    g_x[((size_t)bb * 3136 + hh * 56 + gc) * 192 + n] += val;
                } else if (MODE == 2) {
                    g_hid[(size_t)m * 768 + n] = val * 0.5f * (1.f + erff(val * 0.70710678118654752f));
                } else {
                    g_x[(size_t)m * 192 + n] += val;
                }
            }
}

extern "C" void kernel_launch(void* const* d_in, const int* in_sizes, int n_in,
                              void* d_out, int out_size) {
    const float* x     = (const float*)d_in[0];
    const float* n1w   = (const float*)d_in[1];
    const float* n1b   = (const float*)d_in[2];
    const float* qkvw  = (const float*)d_in[3];
    const float* qkvb  = (const float*)d_in[4];
    const float* rpb   = (const float*)d_in[5];
    const float* projw = (const float*)d_in[6];
    const float* projb = (const float*)d_in[7];
    const float* n2w   = (const float*)d_in[8];
    const float* n2b   = (const float*)d_in[9];
    const float* f1w   = (const float*)d_in[10];
    const float* f1b   = (const float*)d_in[11];
    const float* f2w   = (const float*)d_in[12];
    const float* f2b   = (const float*)d_in[13];

    copy_in_kernel<<<18816, 256>>>(x);
    for (int d = 0; d < 2; d++) {
        int shift = d ? 3 : 0;
        ln1_part_kernel<<<12544, 256>>>(n1w + d * 192, n1b + d * 192, shift);
        gemm_tc<0><<<dim3(784, 9), 256>>>(qkvw + (size_t)d * 576 * 192, qkvb + d * 576, 192, 0);
        attn_kernel<<<12288, 256>>>(rpb + d * 169 * 6, shift);
        gemm_tc<1><<<dim3(784, 3), 256>>>(projw + (size_t)d * 192 * 192, projb + d * 192, 192, shift);
        ln2_kernel<<<12544, 256>>>(n2w + d * 192, n2b + d * 192);
        gemm_tc<2><<<dim3(784, 12), 256>>>(f1w + (size_t)d * 768 * 192, f1b + d * 768, 192, 0);
        gemm_tc<3><<<dim3(784, 3), 256>>>(f2w + (size_t)d * 192 * 768, f2b + d * 192, 768, 0);
    }
    copy_out_kernel<<<18816, 256>>>((float*)d_out);
}

// round 6
// speedup vs baseline: 1.6598x; 1.2616x over previous
#include <cuda_runtime.h>
#include <math.h>

#define TOK 100352
#define SCALE 0.17677669529663687f

__device__ float g_x[19267584];
__device__ float g_hwin[19267584];
__device__ float g_q[19267584];
__device__ float g_k[19267584];
__device__ float g_v[19267584];
__device__ float g_attnout[19267584];
__device__ float g_ln2[19267584];
__device__ float g_hid[77070336];

__device__ __forceinline__ float warp_sum(float v) {
#pragma unroll
    for (int o = 16; o; o >>= 1) v += __shfl_xor_sync(0xffffffffu, v, o);
    return v;
}
__device__ __forceinline__ float warp_max(float v) {
#pragma unroll
    for (int o = 16; o; o >>= 1) v = fmaxf(v, __shfl_xor_sync(0xffffffffu, v, o));
    return v;
}

__device__ __forceinline__ unsigned f2tf32(float f) {
    unsigned r;
    asm("cvt.rna.tf32.f32 %0, %1;" : "=r"(r) : "f"(f));
    return r;
}

// LN1 + shift + window partition. xin != null => read input tensor (layer 0).
__global__ void ln1_part_kernel(const float* __restrict__ w, const float* __restrict__ b,
                                int shift, const float* __restrict__ xin) {
    int gw = (blockIdx.x * blockDim.x + threadIdx.x) >> 5;
    int lane = threadIdx.x & 31;
    if (gw >= TOK) return;
    int win = gw / 49, tok = gw % 49;
    int bb = win >> 6, w64 = win & 63;
    int wh = w64 >> 3, wwi = w64 & 7;
    int ii = tok / 7, jj = tok % 7;
    int sh = (wh * 7 + ii + shift) % 56;
    int sw = (wwi * 7 + jj + shift) % 56;
    const float* base = xin ? xin : g_x;
    const float* src = base + ((size_t)bb * 3136 + sh * 56 + sw) * 192;
    float v[6];
    float s = 0.f;
#pragma unroll
    for (int q = 0; q < 6; q++) { v[q] = src[lane + q * 32]; s += v[q]; }
    s = warp_sum(s);
    float mean = s * (1.f / 192.f);
    float ss = 0.f;
#pragma unroll
    for (int q = 0; q < 6; q++) { float d = v[q] - mean; ss += d * d; }
    ss = warp_sum(ss);
    float rstd = rsqrtf(ss * (1.f / 192.f) + 1e-5f);
    float* dst = g_hwin + (size_t)gw * 192;
#pragma unroll
    for (int q = 0; q < 6; q++) {
        int c = lane + q * 32;
        dst[c] = (v[q] - mean) * rstd * w[c] + b[c];
    }
}

__global__ void ln2_kernel(const float* __restrict__ w, const float* __restrict__ b) {
    int gw = (blockIdx.x * blockDim.x + threadIdx.x) >> 5;
    int lane = threadIdx.x & 31;
    if (gw >= TOK) return;
    const float* src = g_x + (size_t)gw * 192;
    float v[6];
    float s = 0.f;
#pragma unroll
    for (int q = 0; q < 6; q++) { v[q] = src[lane + q * 32]; s += v[q]; }
    s = warp_sum(s);
    float mean = s * (1.f / 192.f);
    float ss = 0.f;
#pragma unroll
    for (int q = 0; q < 6; q++) { float d = v[q] - mean; ss += d * d; }
    ss = warp_sum(ss);
    float rstd = rsqrtf(ss * (1.f / 192.f) + 1e-5f);
    float* dst = g_ln2 + (size_t)gw * 192;
#pragma unroll
    for (int q = 0; q < 6; q++) {
        int c = lane + q * 32;
        dst[c] = (v[q] - mean) * rstd * w[c] + b[c];
    }
}

__device__ __forceinline__ int reg3(int h) { return h < 49 ? 0 : (h < 53 ? 1 : 2); }

// Register-tiled attention: thread (ty,tx) owns rows i=ty+8r (r<7), cols j=tx, tx+32.
__global__ void __launch_bounds__(256) attn_kernel(const float* __restrict__ rpb, int shift) {
    __shared__ float qs[1792];   // 56x32, rows 49..55 zeroed
    __shared__ float ks[1568];   // [d][j] stride 49
    __shared__ float vs[1568];   // [j][d]
    __shared__ float P[2744];    // 56x49
    int bid = blockIdx.x;
    int win = bid / 6, head = bid % 6;
    int tid = threadIdx.x;
    const float* qg = g_q + (size_t)bid * 1568;
    const float* kg = g_k + (size_t)bid * 1568;
    const float* vg = g_v + (size_t)bid * 1568;
    for (int idx = tid; idx < 1568; idx += 256) {
        qs[idx] = qg[idx];
        int j = idx >> 5, dd = idx & 31;
        ks[dd * 49 + j] = kg[idx];
        vs[idx] = vg[idx];
    }
    for (int idx = 1568 + tid; idx < 1792; idx += 256) qs[idx] = 0.f;
    __syncthreads();

    int ty = tid >> 5, tx = tid & 31;
    int j1 = tx + 32;
    bool has1 = (tx < 17);
    int yj0 = tx / 7, xj0 = tx % 7;
    int yj1 = has1 ? j1 / 7 : 0, xj1 = has1 ? j1 % 7 : 0;
    int w64 = win & 63, wh = w64 >> 3, wwi = w64 & 7;
    int rj0 = 0, rj1 = 0;
    if (shift) {
        rj0 = reg3(wh * 7 + yj0) * 3 + reg3(wwi * 7 + xj0);
        rj1 = reg3(wh * 7 + yj1) * 3 + reg3(wwi * 7 + xj1);
    }

    float s0[7], s1[7];
#pragma unroll
    for (int r = 0; r < 7; r++) { s0[r] = 0.f; s1[r] = 0.f; }
#pragma unroll 4
    for (int d = 0; d < 32; d++) {
        float k0 = ks[d * 49 + tx];
        float k1 = has1 ? ks[d * 49 + j1] : 0.f;
#pragma unroll
        for (int r = 0; r < 7; r++) {
            float qv = qs[(ty + 8 * r) * 32 + d];
            s0[r] += qv * k0;
            s1[r] += qv * k1;
        }
    }

#pragma unroll
    for (int r = 0; r < 7; r++) {
        int i = ty + 8 * r;
        float b0 = 0.f, b1 = 0.f, m0 = 0.f, m1 = 0.f;
        if (i < 49) {
            int yi = i / 7, xi = i % 7;
            b0 = rpb[((yi - yj0 + 6) * 13 + (xi - xj0 + 6)) * 6 + head];
            if (has1) b1 = rpb[((yi - yj1 + 6) * 13 + (xi - xj1 + 6)) * 6 + head];
            if (shift) {
                int ri = reg3(wh * 7 + yi) * 3 + reg3(wwi * 7 + xi);
                if (ri != rj0) m0 = -100.f;
                if (ri != rj1) m1 = -100.f;
            }
        }
        float v0 = s0[r] + b0 + m0;
        float v1 = s1[r] + b1 + m1;
        float mx = warp_max(fmaxf(v0, has1 ? v1 : -1e30f));
        float e0 = __expf(v0 - mx);
        float e1 = has1 ? __expf(v1 - mx) : 0.f;
        float sm = warp_sum(e0 + e1);
        float inv = 1.f / sm;
        if (i < 49) {
            P[i * 49 + tx] = e0 * inv;
            if (has1) P[i * 49 + j1] = e1 * inv;
        }
    }
    __syncthreads();

    float o[7] = {0.f, 0.f, 0.f, 0.f, 0.f, 0.f, 0.f};
#pragma unroll 7
    for (int j = 0; j < 49; j++) {
        float vv = vs[j * 32 + tx];
#pragma unroll
        for (int r = 0; r < 7; r++) {
            int i = ty + 8 * r;
            o[r] += ((i < 49) ? P[i * 49 + j] : 0.f) * vv;
        }
    }
#pragma unroll
    for (int r = 0; r < 7; r++) {
        int i = ty + 8 * r;
        if (i < 49)
            g_attnout[((size_t)(win * 49 + i)) * 192 + head * 32 + tx] = o[r];
    }
}

// ------------- tf32 tensor-core GEMM, 256x64 tile, BK=16, conflict-free strides -------------
#define ASTRIDE 264   // ≡ 8 (mod 32): frag-load bank = tg*8+g, perfect permutation
#define BSTRIDE 72

template <int MODE>
__global__ void __launch_bounds__(256, 2) gemm_tc(const float* __restrict__ W,
                                                  const float* __restrict__ bias,
                                                  int K, int shift,
                                                  const float* __restrict__ xin,
                                                  float* __restrict__ outp) {
    __shared__ unsigned As[2][16 * ASTRIDE];
    __shared__ unsigned Bs[2][16 * BSTRIDE];
    const float* A = (MODE == 0) ? g_hwin : (MODE == 1) ? g_attnout : (MODE == 2) ? g_ln2 : g_hid;
    const int bm = blockIdx.x * 256;
    const int bn = blockIdx.y * 64;
    const int tid = threadIdx.x;
    const int warp = tid >> 5, lane = tid & 31;
    const int wm = warp >> 1, wn = warp & 1;   // 4 x 2 warps, each 64x32 of C
    const int g = lane >> 2, tg = lane & 3;

    const float* Arow = A + (size_t)(bm + tid) * K;       // one full row slab per thread
    const int bn0 = tid & 63, bk4 = (tid >> 6) * 4;
    const float* Wrow = W + (size_t)(bn + bn0) * K + bk4;

    float acc[4][4][4];
#pragma unroll
    for (int i = 0; i < 4; i++)
#pragma unroll
        for (int j = 0; j < 4; j++)
#pragma unroll
            for (int r = 0; r < 4; r++) acc[i][j][r] = 0.f;

    const int steps = K >> 4;
    float4 ra[4];
    float4 rbv;
#pragma unroll
    for (int q = 0; q < 4; q++) ra[q] = *(const float4*)(Arow + q * 4);
    rbv = *(const float4*)Wrow;
    {
        unsigned* a = As[0];
#pragma unroll
        for (int q = 0; q < 4; q++) {
            a[(q * 4 + 0) * ASTRIDE + tid] = f2tf32(ra[q].x);
            a[(q * 4 + 1) * ASTRIDE + tid] = f2tf32(ra[q].y);
            a[(q * 4 + 2) * ASTRIDE + tid] = f2tf32(ra[q].z);
            a[(q * 4 + 3) * ASTRIDE + tid] = f2tf32(ra[q].w);
        }
        unsigned* bp = Bs[0];
        bp[(bk4 + 0) * BSTRIDE + bn0] = f2tf32(rbv.x);
        bp[(bk4 + 1) * BSTRIDE + bn0] = f2tf32(rbv.y);
        bp[(bk4 + 2) * BSTRIDE + bn0] = f2tf32(rbv.z);
        bp[(bk4 + 3) * BSTRIDE + bn0] = f2tf32(rbv.w);
    }
    __syncthreads();

    for (int it = 0; it < steps; it++) {
        const int cur = it & 1;
        const bool more = (it + 1) < steps;
        if (more) {
            int ko = (it + 1) << 4;
#pragma unroll
            for (int q = 0; q < 4; q++) ra[q] = *(const float4*)(Arow + ko + q * 4);
            rbv = *(const float4*)(Wrow + ko);
        }
        const unsigned* as = As[cur];
        const unsigned* bs = Bs[cur];
#pragma unroll
        for (int kk = 0; kk < 2; kk++) {
            const int k0 = kk * 8 + tg;
            unsigned af[4][4], bf[4][2];
#pragma unroll
            for (int mt = 0; mt < 4; mt++) {
                int rb = wm * 64 + mt * 16 + g;
                af[mt][0] = as[k0 * ASTRIDE + rb];
                af[mt][1] = as[k0 * ASTRIDE + rb + 8];
                af[mt][2] = as[(k0 + 4) * ASTRIDE + rb];
                af[mt][3] = as[(k0 + 4) * ASTRIDE + rb + 8];
            }
#pragma unroll
            for (int nt = 0; nt < 4; nt++) {
                int nb = wn * 32 + nt * 8 + g;
                bf[nt][0] = bs[k0 * BSTRIDE + nb];
                bf[nt][1] = bs[(k0 + 4) * BSTRIDE + nb];
            }
#pragma unroll
            for (int mt = 0; mt < 4; mt++)
#pragma unroll
                for (int nt = 0; nt < 4; nt++) {
                    asm volatile(
                        "mma.sync.aligned.m16n8k8.row.col.f32.tf32.tf32.f32 "
                        "{%0,%1,%2,%3}, {%4,%5,%6,%7}, {%8,%9}, {%0,%1,%2,%3};\n"
                        : "+f"(acc[mt][nt][0]), "+f"(acc[mt][nt][1]),
                          "+f"(acc[mt][nt][2]), "+f"(acc[mt][nt][3])
                        : "r"(af[mt][0]), "r"(af[mt][1]), "r"(af[mt][2]), "r"(af[mt][3]),
                          "r"(bf[nt][0]), "r"(bf[nt][1]));
                }
        }
        if (more) {
            unsigned* a = As[cur ^ 1];
#pragma unroll
            for (int q = 0; q < 4; q++) {
                a[(q * 4 + 0) * ASTRIDE + tid] = f2tf32(ra[q].x);
                a[(q * 4 + 1) * ASTRIDE + tid] = f2tf32(ra[q].y);
                a[(q * 4 + 2) * ASTRIDE + tid] = f2tf32(ra[q].z);
                a[(q * 4 + 3) * ASTRIDE + tid] = f2tf32(ra[q].w);
            }
            unsigned* bp = Bs[cur ^ 1];
            bp[(bk4 + 0) * BSTRIDE + bn0] = f2tf32(rbv.x);
            bp[(bk4 + 1) * BSTRIDE + bn0] = f2tf32(rbv.y);
            bp[(bk4 + 2) * BSTRIDE + bn0] = f2tf32(rbv.z);
            bp[(bk4 + 3) * BSTRIDE + bn0] = f2tf32(rbv.w);
            __syncthreads();
        }
    }

#pragma unroll
    for (int mt = 0; mt < 4; mt++)
#pragma unroll
        for (int nt = 0; nt < 4; nt++)
#pragma unroll
            for (int r = 0; r < 4; r++) {
                int m = bm + wm * 64 + mt * 16 + g + ((r >= 2) ? 8 : 0);
                int n = bn + wn * 32 + nt * 8 + tg * 2 + (r & 1);
                float val = acc[mt][nt][r] + bias[n];
                if (MODE == 0) {
                    int part = n / 192, rem = n % 192, head = rem >> 5, dd = rem & 31;
                    int win = m / 49, tok = m % 49;
                    size_t dst = ((size_t)(win * 6 + head) * 49 + tok) * 32 + dd;
                    if (part == 0) g_q[dst] = val * SCALE;
                    else if (part == 1) g_k[dst] = val;
                    else g_v[dst] = val;
                } else if (MODE == 1) {
                    int win = m / 49, tok = m % 49;
                    int bb = win >> 6, w64 = win & 63, wh = w64 >> 3, wwi = w64 & 7;
                    int ii = tok / 7, jj = tok % 7;
                    int hh = wh * 7 + ii, gc = wwi * 7 + jj;
                    if (shift) { hh = (hh + 7) % 56; gc = (gc + 7) % 56; }
                    size_t dst = ((size_t)bb * 3136 + hh * 56 + gc) * 192 + n;
                    g_x[dst] = (xin ? xin[dst] : g_x[dst]) + val;
                } else if (MODE == 2) {
                    g_hid[(size_t)m * 768 + n] = val * 0.5f * (1.f + erff(val * 0.70710678118654752f));
                } else {
                    size_t dst = (size_t)m * 192 + n;
                    float res = g_x[dst] + val;
                    if (outp) outp[dst] = res;
                    else g_x[dst] = res;
                }
            }
}

extern "C" void kernel_launch(void* const* d_in, const int* in_sizes, int n_in,
                              void* d_out, int out_size) {
    const float* x     = (const float*)d_in[0];
    const float* n1w   = (const float*)d_in[1];
    const float* n1b   = (const float*)d_in[2];
    const float* qkvw  = (const float*)d_in[3];
    const float* qkvb  = (const float*)d_in[4];
    const float* rpb   = (const float*)d_in[5];
    const float* projw = (const float*)d_in[6];
    const float* projb = (const float*)d_in[7];
    const float* n2w   = (const float*)d_in[8];
    const float* n2b   = (const float*)d_in[9];
    const float* f1w   = (const float*)d_in[10];
    const float* f1b   = (const float*)d_in[11];
    const float* f2w   = (const float*)d_in[12];
    const float* f2b   = (const float*)d_in[13];

    for (int d = 0; d < 2; d++) {
        int shift = d ? 3 : 0;
        const float* xin = (d == 0) ? x : nullptr;
        float* outp = (d == 1) ? (float*)d_out : nullptr;
        ln1_part_kernel<<<12544, 256>>>(n1w + d * 192, n1b + d * 192, shift, xin);
        gemm_tc<0><<<dim3(392, 9), 256>>>(qkvw + (size_t)d * 576 * 192, qkvb + d * 576, 192, 0, nullptr, nullptr);
        attn_kernel<<<12288, 256>>>(rpb + d * 169 * 6, shift);
        gemm_tc<1><<<dim3(392, 3), 256>>>(projw + (size_t)d * 192 * 192, projb + d * 192, 192, shift, xin, nullptr);
        ln2_kernel<<<12544, 256>>>(n2w + d * 192, n2b + d * 192);
        gemm_tc<2><<<dim3(392, 12), 256>>>(f1w + (size_t)d * 768 * 192, f1b + d * 768, 192, 0, nullptr, nullptr);
        gemm_tc<3><<<dim3(392, 3), 256>>>(f2w + (size_t)d * 192 * 768, f2b + d * 192, 768, 0, nullptr, outp);
    }
}

// round 8
// speedup vs baseline: 2.4882x; 1.4991x over previous
#include <cuda_runtime.h>
#include <math.h>
#include <stdint.h>

#define TOK 100352
#define SCALE 0.17677669529663687f

__device__ float g_x[19267584];
__device__ float g_hwin[19267584];
__device__ float g_q[19267584];
__device__ float g_k[19267584];
__device__ float g_v[19267584];
__device__ float g_attnout[19267584];
__device__ float g_ln2[19267584];
__device__ float g_hid[77070336];
__device__ float g_wcv[884736];   // tf32-rounded weights: qkv|proj|f1|f2 (both layers)

__device__ __forceinline__ float warp_sum(float v) {
#pragma unroll
    for (int o = 16; o; o >>= 1) v += __shfl_xor_sync(0xffffffffu, v, o);
    return v;
}
__device__ __forceinline__ float warp_max(float v) {
#pragma unroll
    for (int o = 16; o; o >>= 1) v = fmaxf(v, __shfl_xor_sync(0xffffffffu, v, o));
    return v;
}
__device__ __forceinline__ float f2tf32f(float f) {
    unsigned r;
    asm("cvt.rna.tf32.f32 %0, %1;" : "=r"(r) : "f"(f));
    return __uint_as_float(r);
}
__device__ __forceinline__ uint32_t smem_u32(const void* p) {
    uint32_t a;
    asm("{ .reg .u64 t; cvta.to.shared.u64 t, %1; cvt.u32.u64 %0, t; }" : "=r"(a) : "l"(p));
    return a;
}
__device__ __forceinline__ void cpa16(uint32_t dst, const float* src) {
    asm volatile("cp.async.cg.shared.global [%0], [%1], 16;" :: "r"(dst), "l"(src));
}

// ---------------- weight pre-convert (fp32 -> tf32-rounded fp32) ----------------
__global__ void convw_kernel(const float* __restrict__ s, float* __restrict__ d, int n4) {
    int i = blockIdx.x * blockDim.x + threadIdx.x;
    if (i >= n4) return;
    float4 v = ((const float4*)s)[i];
    v.x = f2tf32f(v.x); v.y = f2tf32f(v.y); v.z = f2tf32f(v.z); v.w = f2tf32f(v.w);
    ((float4*)d)[i] = v;
}

// ---------------- LN kernels (tf32-rounded outputs) ----------------
__global__ void ln1_part_kernel(const float* __restrict__ w, const float* __restrict__ b,
                                int shift, const float* __restrict__ xin) {
    int gw = (blockIdx.x * blockDim.x + threadIdx.x) >> 5;
    int lane = threadIdx.x & 31;
    if (gw >= TOK) return;
    int win = gw / 49, tok = gw % 49;
    int bb = win >> 6, w64 = win & 63;
    int wh = w64 >> 3, wwi = w64 & 7;
    int ii = tok / 7, jj = tok % 7;
    int sh = (wh * 7 + ii + shift) % 56;
    int sw = (wwi * 7 + jj + shift) % 56;
    const float* base = xin ? xin : g_x;
    const float* src = base + ((size_t)bb * 3136 + sh * 56 + sw) * 192;
    float v[6];
    float s = 0.f;
#pragma unroll
    for (int q = 0; q < 6; q++) { v[q] = src[lane + q * 32]; s += v[q]; }
    s = warp_sum(s);
    float mean = s * (1.f / 192.f);
    float ss = 0.f;
#pragma unroll
    for (int q = 0; q < 6; q++) { float d = v[q] - mean; ss += d * d; }
    ss = warp_sum(ss);
    float rstd = rsqrtf(ss * (1.f / 192.f) + 1e-5f);
    float* dst = g_hwin + (size_t)gw * 192;
#pragma unroll
    for (int q = 0; q < 6; q++) {
        int c = lane + q * 32;
        dst[c] = f2tf32f((v[q] - mean) * rstd * w[c] + b[c]);
    }
}

__global__ void ln2_kernel(const float* __restrict__ w, const float* __restrict__ b) {
    int gw = (blockIdx.x * blockDim.x + threadIdx.x) >> 5;
    int lane = threadIdx.x & 31;
    if (gw >= TOK) return;
    const float* src = g_x + (size_t)gw * 192;
    float v[6];
    float s = 0.f;
#pragma unroll
    for (int q = 0; q < 6; q++) { v[q] = src[lane + q * 32]; s += v[q]; }
    s = warp_sum(s);
    float mean = s * (1.f / 192.f);
    float ss = 0.f;
#pragma unroll
    for (int q = 0; q < 6; q++) { float d = v[q] - mean; ss += d * d; }
    ss = warp_sum(ss);
    float rstd = rsqrtf(ss * (1.f / 192.f) + 1e-5f);
    float* dst = g_ln2 + (size_t)gw * 192;
#pragma unroll
    for (int q = 0; q < 6; q++) {
        int c = lane + q * 32;
        dst[c] = f2tf32f((v[q] - mean) * rstd * w[c] + b[c]);
    }
}

__device__ __forceinline__ int reg3(int h) { return h < 49 ? 0 : (h < 53 ? 1 : 2); }

// ---------------- attention (tf32-rounded output) ----------------
__global__ void __launch_bounds__(256) attn_kernel(const float* __restrict__ rpb, int shift) {
    __shared__ float qs[1792];
    __shared__ float ks[1568];
    __shared__ float vs[1568];
    __shared__ float P[2744];
    int bid = blockIdx.x;
    int win = bid / 6, head = bid % 6;
    int tid = threadIdx.x;
    const float* qg = g_q + (size_t)bid * 1568;
    const float* kg = g_k + (size_t)bid * 1568;
    const float* vg = g_v + (size_t)bid * 1568;
    for (int idx = tid; idx < 1568; idx += 256) {
        qs[idx] = qg[idx];
        int j = idx >> 5, dd = idx & 31;
        ks[dd * 49 + j] = kg[idx];
        vs[idx] = vg[idx];
    }
    for (int idx = 1568 + tid; idx < 1792; idx += 256) qs[idx] = 0.f;
    __syncthreads();

    int ty = tid >> 5, tx = tid & 31;
    int j1 = tx + 32;
    bool has1 = (tx < 17);
    int yj0 = tx / 7, xj0 = tx % 7;
    int yj1 = has1 ? j1 / 7 : 0, xj1 = has1 ? j1 % 7 : 0;
    int w64 = win & 63, wh = w64 >> 3, wwi = w64 & 7;
    int rj0 = 0, rj1 = 0;
    if (shift) {
        rj0 = reg3(wh * 7 + yj0) * 3 + reg3(wwi * 7 + xj0);
        rj1 = reg3(wh * 7 + yj1) * 3 + reg3(wwi * 7 + xj1);
    }

    float s0[7], s1[7];
#pragma unroll
    for (int r = 0; r < 7; r++) { s0[r] = 0.f; s1[r] = 0.f; }
#pragma unroll 4
    for (int d = 0; d < 32; d++) {
        float k0 = ks[d * 49 + tx];
        float k1 = has1 ? ks[d * 49 + j1] : 0.f;
#pragma unroll
        for (int r = 0; r < 7; r++) {
            float qv = qs[(ty + 8 * r) * 32 + d];
            s0[r] += qv * k0;
            s1[r] += qv * k1;
        }
    }

#pragma unroll
    for (int r = 0; r < 7; r++) {
        int i = ty + 8 * r;
        float b0 = 0.f, b1 = 0.f, m0 = 0.f, m1 = 0.f;
        if (i < 49) {
            int yi = i / 7, xi = i % 7;
            b0 = rpb[((yi - yj0 + 6) * 13 + (xi - xj0 + 6)) * 6 + head];
            if (has1) b1 = rpb[((yi - yj1 + 6) * 13 + (xi - xj1 + 6)) * 6 + head];
            if (shift) {
                int ri = reg3(wh * 7 + yi) * 3 + reg3(wwi * 7 + xi);
                if (ri != rj0) m0 = -100.f;
                if (ri != rj1) m1 = -100.f;
            }
        }
        float v0 = s0[r] + b0 + m0;
        float v1 = s1[r] + b1 + m1;
        float mx = warp_max(fmaxf(v0, has1 ? v1 : -1e30f));
        float e0 = __expf(v0 - mx);
        float e1 = has1 ? __expf(v1 - mx) : 0.f;
        float sm = warp_sum(e0 + e1);
        float inv = 1.f / sm;
        if (i < 49) {
            P[i * 49 + tx] = e0 * inv;
            if (has1) P[i * 49 + j1] = e1 * inv;
        }
    }
    __syncthreads();

    float o[7] = {0.f, 0.f, 0.f, 0.f, 0.f, 0.f, 0.f};
#pragma unroll 7
    for (int j = 0; j < 49; j++) {
        float vv = vs[j * 32 + tx];
#pragma unroll
        for (int r = 0; r < 7; r++) {
            int i = ty + 8 * r;
            o[r] += ((i < 49) ? P[i * 49 + j] : 0.f) * vv;
        }
    }
#pragma unroll
    for (int r = 0; r < 7; r++) {
        int i = ty + 8 * r;
        if (i < 49)
            g_attnout[((size_t)(win * 49 + i)) * 192 + head * 32 + tx] = f2tf32f(o[r]);
    }
}

// -------- tf32 mma.sync GEMM: CTA 256x64, 128 threads, warp tile 64x64, cp.async --------
// smem layout per buffer: A [256 rows][20 words], B [64 rows][20 words]; 2 buffers.
// A bytes: 20480, B bytes: 5120, buffer: 25600, total dynamic smem: 51200.
#define GT_DSMEM 51200

template <int MODE>
__global__ void __launch_bounds__(128) gemm_tc(const float* __restrict__ Wt,
                                               const float* __restrict__ bias,
                                               int K, int shift,
                                               const float* __restrict__ xin,
                                               float* __restrict__ outp) {
    extern __shared__ unsigned sm[];
    const float* A = (MODE == 0) ? g_hwin : (MODE == 1) ? g_attnout : (MODE == 2) ? g_ln2 : g_hid;
    const int bm = blockIdx.x * 256;
    const int bn = blockIdx.y * 64;
    const int tid = threadIdx.x, wid = tid >> 5, lane = tid & 31;
    const int g = lane >> 2, tg = lane & 3;
    const uint32_t sbase = smem_u32(sm);
    const float* Abase = A + (size_t)bm * K;
    const float* Bbase = Wt + (size_t)bn * K;
    const int NCH = K >> 4;

    float acc[4][8][4];
#pragma unroll
    for (int i = 0; i < 4; i++)
#pragma unroll
        for (int j = 0; j < 8; j++)
#pragma unroll
            for (int r = 0; r < 4; r++) acc[i][j][r] = 0.f;

    auto issue = [&](int c) {
        uint32_t sb = sbase + (c & 1) * 25600;
        const float* Ab = Abase + c * 16;
#pragma unroll
        for (int i = 0; i < 8; i++) {
            int f4 = tid + i * 128, row = f4 >> 2, kq = (f4 & 3) * 4;
            cpa16(sb + (row * 20 + kq) * 4, Ab + (size_t)row * K + kq);
        }
        const float* Bb = Bbase + c * 16;
#pragma unroll
        for (int i = 0; i < 2; i++) {
            int f4 = tid + i * 128, row = f4 >> 2, kq = (f4 & 3) * 4;
            cpa16(sb + 20480 + (row * 20 + kq) * 4, Bb + (size_t)row * K + kq);
        }
        asm volatile("cp.async.commit_group;" ::: "memory");
    };

    issue(0);
    issue(1);

    for (int c = 0; c < NCH; c++) {
        if (c + 1 < NCH) asm volatile("cp.async.wait_group 1;" ::: "memory");
        else             asm volatile("cp.async.wait_group 0;" ::: "memory");
        __syncthreads();
        const unsigned* as = sm + (c & 1) * 6400;
        const unsigned* bs = as + 5120;
#pragma unroll
        for (int kk = 0; kk < 2; kk++) {
            const int k0 = kk * 8 + tg;
            unsigned af[4][4], bf[8][2];
#pragma unroll
            for (int mt = 0; mt < 4; mt++) {
                int rb = wid * 64 + mt * 16 + g;
                af[mt][0] = as[rb * 20 + k0];
                af[mt][1] = as[(rb + 8) * 20 + k0];
                af[mt][2] = as[rb * 20 + k0 + 4];
                af[mt][3] = as[(rb + 8) * 20 + k0 + 4];
            }
#pragma unroll
            for (int nt = 0; nt < 8; nt++) {
                int nb = nt * 8 + g;
                bf[nt][0] = bs[nb * 20 + k0];
                bf[nt][1] = bs[nb * 20 + k0 + 4];
            }
#pragma unroll
            for (int mt = 0; mt < 4; mt++)
#pragma unroll
                for (int nt = 0; nt < 8; nt++) {
                    asm volatile(
                        "mma.sync.aligned.m16n8k8.row.col.f32.tf32.tf32.f32 "
                        "{%0,%1,%2,%3}, {%4,%5,%6,%7}, {%8,%9}, {%0,%1,%2,%3};\n"
                        : "+f"(acc[mt][nt][0]), "+f"(acc[mt][nt][1]),
                          "+f"(acc[mt][nt][2]), "+f"(acc[mt][nt][3])
                        : "r"(af[mt][0]), "r"(af[mt][1]), "r"(af[mt][2]), "r"(af[mt][3]),
                          "r"(bf[nt][0]), "r"(bf[nt][1]));
                }
        }
        __syncthreads();
        if (c + 2 < NCH) issue(c + 2);
    }

    // epilogue: thread holds rows bm+wid*64+mt*16+g(+8), col pairs bn+nt*8+tg*2
#pragma unroll
    for (int mt = 0; mt < 4; mt++)
#pragma unroll
        for (int rr = 0; rr < 2; rr++) {
            int m = bm + wid * 64 + mt * 16 + g + rr * 8;
            if (MODE == 0) {
                int win = m / 49, tok = m % 49;
#pragma unroll
                for (int nt = 0; nt < 8; nt++) {
                    int c0 = nt * 8 + tg * 2;
                    int n = bn + c0;
                    int part = n / 192, rem = n % 192, head = rem >> 5, dd = rem & 31;
                    size_t dst = ((size_t)(win * 6 + head) * 49 + tok) * 32 + dd;
                    float v0 = acc[mt][nt][rr * 2] + bias[n];
                    float v1 = acc[mt][nt][rr * 2 + 1] + bias[n + 1];
                    if (part == 0)      *(float2*)(g_q + dst) = make_float2(v0 * SCALE, v1 * SCALE);
                    else if (part == 1) *(float2*)(g_k + dst) = make_float2(v0, v1);
                    else                *(float2*)(g_v + dst) = make_float2(v0, v1);
                }
            } else if (MODE == 1) {
                int win = m / 49, tok = m % 49;
                int bb = win >> 6, w64 = win & 63, wh = w64 >> 3, wwi = w64 & 7;
                int ii = tok / 7, jj = tok % 7;
                int hh = wh * 7 + ii, gc = wwi * 7 + jj;
                if (shift) { hh = (hh + 7) % 56; gc = (gc + 7) % 56; }
                size_t rowo = ((size_t)bb * 3136 + hh * 56 + gc) * 192 + bn;
                const float* resp = (xin ? xin : (const float*)g_x) + rowo;
#pragma unroll
                for (int nt = 0; nt < 8; nt++) {
                    int c0 = nt * 8 + tg * 2;
                    float2 rv = *(const float2*)(resp + c0);
                    float2 bv = *(const float2*)(bias + bn + c0);
                    float v0 = acc[mt][nt][rr * 2] + bv.x + rv.x;
                    float v1 = acc[mt][nt][rr * 2 + 1] + bv.y + rv.y;
                    *(float2*)(g_x + rowo + c0) = make_float2(v0, v1);
                }
            } else if (MODE == 2) {
                float* hrow = g_hid + (size_t)m * 768 + bn;
#pragma unroll
                for (int nt = 0; nt < 8; nt++) {
                    int c0 = nt * 8 + tg * 2;
                    float2 bv = *(const float2*)(bias + bn + c0);
                    float v0 = acc[mt][nt][rr * 2] + bv.x;
                    float v1 = acc[mt][nt][rr * 2 + 1] + bv.y;
                    v0 = v0 * 0.5f * (1.f + erff(v0 * 0.70710678118654752f));
                    v1 = v1 * 0.5f * (1.f + erff(v1 * 0.70710678118654752f));
                    *(float2*)(hrow + c0) = make_float2(f2tf32f(v0), f2tf32f(v1));
                }
            } else {
                size_t rowo = (size_t)m * 192 + bn;
                float* dst = outp ? outp : g_x;
#pragma unroll
                for (int nt = 0; nt < 8; nt++) {
                    int c0 = nt * 8 + tg * 2;
                    float2 rv = *(const float2*)(g_x + rowo + c0);
                    float2 bv = *(const float2*)(bias + bn + c0);
                    float v0 = acc[mt][nt][rr * 2] + bv.x + rv.x;
                    float v1 = acc[mt][nt][rr * 2 + 1] + bv.y + rv.y;
                    *(float2*)(dst + rowo + c0) = make_float2(v0, v1);
                }
            }
        }
}

extern "C" void kernel_launch(void* const* d_in, const int* in_sizes, int n_in,
                              void* d_out, int out_size) {
    const float* x     = (const float*)d_in[0];
    const float* n1w   = (const float*)d_in[1];
    const float* n1b   = (const float*)d_in[2];
    const float* qkvw  = (const float*)d_in[3];
    const float* qkvb  = (const float*)d_in[4];
    const float* rpb   = (const float*)d_in[5];
    const float* projw = (const float*)d_in[6];
    const float* projb = (const float*)d_in[7];
    const float* n2w   = (const float*)d_in[8];
    const float* n2b   = (const float*)d_in[9];
    const float* f1w   = (const float*)d_in[10];
    const float* f1b   = (const float*)d_in[11];
    const float* f2w   = (const float*)d_in[12];
    const float* f2b   = (const float*)d_in[13];

    cudaFuncSetAttribute(gemm_tc<0>, cudaFuncAttributeMaxDynamicSharedMemorySize, GT_DSMEM);
    cudaFuncSetAttribute(gemm_tc<1>, cudaFuncAttributeMaxDynamicSharedMemorySize, GT_DSMEM);
    cudaFuncSetAttribute(gemm_tc<2>, cudaFuncAttributeMaxDynamicSharedMemorySize, GT_DSMEM);
    cudaFuncSetAttribute(gemm_tc<3>, cudaFuncAttributeMaxDynamicSharedMemorySize, GT_DSMEM);

    // weight pre-convert (tf32-rna rounding), both layers each
    float* wq = nullptr; cudaGetSymbolAddress((void**)&wq, g_wcv);
    float* wp = wq + 221184;
    float* w1 = wq + 294912;
    float* w2 = wq + 589824;
    convw_kernel<<<216, 256>>>(qkvw,  wq, 55296);
    convw_kernel<<<72,  256>>>(projw, wp, 18432);
    convw_kernel<<<288, 256>>>(f1w,   w1, 73728);
    convw_kernel<<<288, 256>>>(f2w,   w2, 73728);

    for (int d = 0; d < 2; d++) {
        int shift = d ? 3 : 0;
        const float* xin = (d == 0) ? x : nullptr;
        float* outp = (d == 1) ? (float*)d_out : nullptr;
        ln1_part_kernel<<<12544, 256>>>(n1w + d * 192, n1b + d * 192, shift, xin);
        gemm_tc<0><<<dim3(392, 9), 128, GT_DSMEM>>>(wq + (size_t)d * 110592, qkvb + d * 576, 192, 0, nullptr, nullptr);
        attn_kernel<<<12288, 256>>>(rpb + d * 169 * 6, shift);
        gemm_tc<1><<<dim3(392, 3), 128, GT_DSMEM>>>(wp + (size_t)d * 36864, projb + d * 192, 192, shift, xin, nullptr);
        ln2_kernel<<<12544, 256>>>(n2w + d * 192, n2b + d * 192);
        gemm_tc<2><<<dim3(392, 12), 128, GT_DSMEM>>>(w1 + (size_t)d * 147456, f1b + d * 768, 192, 0, nullptr, nullptr);
        gemm_tc<3><<<dim3(392, 3), 128, GT_DSMEM>>>(w2 + (size_t)d * 147456, f2b + d * 192, 768, 0, nullptr, outp);
    }
}

// round 9
// speedup vs baseline: 3.4481x; 1.3858x over previous
#include <cuda_runtime.h>
#include <cuda_fp16.h>
#include <math.h>
#include <stdint.h>

#define TOK 100352
#define SCALE 0.17677669529663687f

__device__ float  g_x[19267584];        // fp32 residual stream
__device__ __half g_hwin[19267584];
__device__ float  g_q[19267584];
__device__ float  g_k[19267584];
__device__ float  g_v[19267584];
__device__ __half g_attnout[19267584];
__device__ __half g_ln2[19267584];
__device__ __half g_hid[77070336];
__device__ __half g_wcv[884736];        // fp16 weights: qkv|proj|f1|f2 (both layers)

__device__ __forceinline__ float warp_sum(float v) {
#pragma unroll
    for (int o = 16; o; o >>= 1) v += __shfl_xor_sync(0xffffffffu, v, o);
    return v;
}
__device__ __forceinline__ float warp_max(float v) {
#pragma unroll
    for (int o = 16; o; o >>= 1) v = fmaxf(v, __shfl_xor_sync(0xffffffffu, v, o));
    return v;
}
__device__ __forceinline__ uint32_t smem_u32(const void* p) {
    uint32_t a;
    asm("{ .reg .u64 t; cvta.to.shared.u64 t, %1; cvt.u32.u64 %0, t; }" : "=r"(a) : "l"(p));
    return a;
}
__device__ __forceinline__ void cpa16(uint32_t dst, const void* src) {
    asm volatile("cp.async.cg.shared.global [%0], [%1], 16;" :: "r"(dst), "l"(src));
}

// ---------------- weight pre-convert (fp32 -> fp16) ----------------
__global__ void convw_kernel(const float* __restrict__ s, __half* __restrict__ d, int n4) {
    int i = blockIdx.x * blockDim.x + threadIdx.x;
    if (i >= n4) return;
    float4 v = ((const float4*)s)[i];
    __half2* dp = (__half2*)d + i * 2;
    dp[0] = __floats2half2_rn(v.x, v.y);
    dp[1] = __floats2half2_rn(v.z, v.w);
}

// ---------------- LN kernels (fp16 outputs) ----------------
__global__ void ln1_part_kernel(const float* __restrict__ w, const float* __restrict__ b,
                                int shift, const float* __restrict__ xin) {
    int gw = (blockIdx.x * blockDim.x + threadIdx.x) >> 5;
    int lane = threadIdx.x & 31;
    if (gw >= TOK) return;
    int win = gw / 49, tok = gw % 49;
    int bb = win >> 6, w64 = win & 63;
    int wh = w64 >> 3, wwi = w64 & 7;
    int ii = tok / 7, jj = tok % 7;
    int sh = (wh * 7 + ii + shift) % 56;
    int sw = (wwi * 7 + jj + shift) % 56;
    const float* base = xin ? xin : g_x;
    const float* src = base + ((size_t)bb * 3136 + sh * 56 + sw) * 192;
    float v[6];
    float s = 0.f;
#pragma unroll
    for (int q = 0; q < 6; q++) { v[q] = src[lane + q * 32]; s += v[q]; }
    s = warp_sum(s);
    float mean = s * (1.f / 192.f);
    float ss = 0.f;
#pragma unroll
    for (int q = 0; q < 6; q++) { float d = v[q] - mean; ss += d * d; }
    ss = warp_sum(ss);
    float rstd = rsqrtf(ss * (1.f / 192.f) + 1e-5f);
    __half* dst = g_hwin + (size_t)gw * 192;
#pragma unroll
    for (int q = 0; q < 6; q++) {
        int c = lane + q * 32;
        dst[c] = __float2half((v[q] - mean) * rstd * w[c] + b[c]);
    }
}

__global__ void ln2_kernel(const float* __restrict__ w, const float* __restrict__ b) {
    int gw = (blockIdx.x * blockDim.x + threadIdx.x) >> 5;
    int lane = threadIdx.x & 31;
    if (gw >= TOK) return;
    const float* src = g_x + (size_t)gw * 192;
    float v[6];
    float s = 0.f;
#pragma unroll
    for (int q = 0; q < 6; q++) { v[q] = src[lane + q * 32]; s += v[q]; }
    s = warp_sum(s);
    float mean = s * (1.f / 192.f);
    float ss = 0.f;
#pragma unroll
    for (int q = 0; q < 6; q++) { float d = v[q] - mean; ss += d * d; }
    ss = warp_sum(ss);
    float rstd = rsqrtf(ss * (1.f / 192.f) + 1e-5f);
    __half* dst = g_ln2 + (size_t)gw * 192;
#pragma unroll
    for (int q = 0; q < 6; q++) {
        int c = lane + q * 32;
        dst[c] = __float2half((v[q] - mean) * rstd * w[c] + b[c]);
    }
}

__device__ __forceinline__ int reg3(int h) { return h < 49 ? 0 : (h < 53 ? 1 : 2); }

// ---------------- attention (fp32 in, fp16 out) ----------------
__global__ void __launch_bounds__(256) attn_kernel(const float* __restrict__ rpb, int shift) {
    __shared__ float qs[1792];
    __shared__ float ks[1568];
    __shared__ float vs[1568];
    __shared__ float P[2744];
    int bid = blockIdx.x;
    int win = bid / 6, head = bid % 6;
    int tid = threadIdx.x;
    const float* qg = g_q + (size_t)bid * 1568;
    const float* kg = g_k + (size_t)bid * 1568;
    const float* vg = g_v + (size_t)bid * 1568;
    for (int idx = tid; idx < 1568; idx += 256) {
        qs[idx] = qg[idx];
        int j = idx >> 5, dd = idx & 31;
        ks[dd * 49 + j] = kg[idx];
        vs[idx] = vg[idx];
    }
    for (int idx = 1568 + tid; idx < 1792; idx += 256) qs[idx] = 0.f;
    __syncthreads();

    int ty = tid >> 5, tx = tid & 31;
    int j1 = tx + 32;
    bool has1 = (tx < 17);
    int yj0 = tx / 7, xj0 = tx % 7;
    int yj1 = has1 ? j1 / 7 : 0, xj1 = has1 ? j1 % 7 : 0;
    int w64 = win & 63, wh = w64 >> 3, wwi = w64 & 7;
    int rj0 = 0, rj1 = 0;
    if (shift) {
        rj0 = reg3(wh * 7 + yj0) * 3 + reg3(wwi * 7 + xj0);
        rj1 = reg3(wh * 7 + yj1) * 3 + reg3(wwi * 7 + xj1);
    }

    float s0[7], s1[7];
#pragma unroll
    for (int r = 0; r < 7; r++) { s0[r] = 0.f; s1[r] = 0.f; }
#pragma unroll 4
    for (int d = 0; d < 32; d++) {
        float k0 = ks[d * 49 + tx];
        float k1 = has1 ? ks[d * 49 + j1] : 0.f;
#pragma unroll
        for (int r = 0; r < 7; r++) {
            float qv = qs[(ty + 8 * r) * 32 + d];
            s0[r] += qv * k0;
            s1[r] += qv * k1;
        }
    }

#pragma unroll
    for (int r = 0; r < 7; r++) {
        int i = ty + 8 * r;
        float b0 = 0.f, b1 = 0.f, m0 = 0.f, m1 = 0.f;
        if (i < 49) {
            int yi = i / 7, xi = i % 7;
            b0 = rpb[((yi - yj0 + 6) * 13 + (xi - xj0 + 6)) * 6 + head];
            if (has1) b1 = rpb[((yi - yj1 + 6) * 13 + (xi - xj1 + 6)) * 6 + head];
            if (shift) {
                int ri = reg3(wh * 7 + yi) * 3 + reg3(wwi * 7 + xi);
                if (ri != rj0) m0 = -100.f;
                if (ri != rj1) m1 = -100.f;
            }
        }
        float v0 = s0[r] + b0 + m0;
        float v1 = s1[r] + b1 + m1;
        float mx = warp_max(fmaxf(v0, has1 ? v1 : -1e30f));
        float e0 = __expf(v0 - mx);
        float e1 = has1 ? __expf(v1 - mx) : 0.f;
        float sm = warp_sum(e0 + e1);
        float inv = 1.f / sm;
        if (i < 49) {
            P[i * 49 + tx] = e0 * inv;
            if (has1) P[i * 49 + j1] = e1 * inv;
        }
    }
    __syncthreads();

    float o[7] = {0.f, 0.f, 0.f, 0.f, 0.f, 0.f, 0.f};
#pragma unroll 7
    for (int j = 0; j < 49; j++) {
        float vv = vs[j * 32 + tx];
#pragma unroll
        for (int r = 0; r < 7; r++) {
            int i = ty + 8 * r;
            o[r] += ((i < 49) ? P[i * 49 + j] : 0.f) * vv;
        }
    }
#pragma unroll
    for (int r = 0; r < 7; r++) {
        int i = ty + 8 * r;
        if (i < 49)
            g_attnout[((size_t)(win * 49 + i)) * 192 + head * 32 + tx] = __float2half(o[r]);
    }
}

// -------- fp16 mma.sync GEMM: CTA 256x64, 128 threads, warp tile 64x64, 3-stage cp.async --------
// per buffer: A 256 rows x 40 halves (20 words) = 20480B, B 64 x 40 halves = 5120B; 3 buffers.
#define GT_DSMEM 76800

template <int MODE>
__global__ void __launch_bounds__(128) gemm_tc(const __half* __restrict__ Wt,
                                               const float* __restrict__ bias,
                                               int K, int shift,
                                               const float* __restrict__ xin,
                                               float* __restrict__ outp) {
    extern __shared__ unsigned sm[];
    const __half* A = (MODE == 0) ? g_hwin : (MODE == 1) ? g_attnout : (MODE == 2) ? g_ln2 : g_hid;
    const int bm = blockIdx.x * 256;
    const int bn = blockIdx.y * 64;
    const int tid = threadIdx.x, wid = tid >> 5, lane = tid & 31;
    const int g = lane >> 2, tg = lane & 3;
    const uint32_t sbase = smem_u32(sm);
    const __half* Abase = A + (size_t)bm * K;
    const __half* Bbase = Wt + (size_t)bn * K;
    const int NCH = K >> 5;   // chunks of 32 halves

    float acc[4][8][4];
#pragma unroll
    for (int i = 0; i < 4; i++)
#pragma unroll
        for (int j = 0; j < 8; j++)
#pragma unroll
            for (int r = 0; r < 4; r++) acc[i][j][r] = 0.f;

    auto issue = [&](int c) {
        uint32_t sb = sbase + (c % 3) * 25600;
        const __half* Ab = Abase + c * 32;
#pragma unroll
        for (int i = 0; i < 8; i++) {
            int f8 = tid + i * 128, row = f8 >> 2, ch = f8 & 3;
            cpa16(sb + (row * 20 + ch * 4) * 4, Ab + (size_t)row * K + ch * 8);
        }
        const __half* Bb = Bbase + c * 32;
#pragma unroll
        for (int i = 0; i < 2; i++) {
            int f8 = tid + i * 128, row = f8 >> 2, ch = f8 & 3;
            cpa16(sb + 20480 + (row * 20 + ch * 4) * 4, Bb + (size_t)row * K + ch * 8);
        }
        asm volatile("cp.async.commit_group;" ::: "memory");
    };

    issue(0);
    if (NCH > 1) issue(1);
    if (NCH > 2) issue(2);

    for (int c = 0; c < NCH; c++) {
        if (c + 2 < NCH)      asm volatile("cp.async.wait_group 2;" ::: "memory");
        else if (c + 1 < NCH) asm volatile("cp.async.wait_group 1;" ::: "memory");
        else                  asm volatile("cp.async.wait_group 0;" ::: "memory");
        __syncthreads();
        const unsigned* as = sm + (c % 3) * 6400;
        const unsigned* bs = as + 5120;
#pragma unroll
        for (int s = 0; s < 2; s++) {
            const int k0 = s * 8 + tg;
            unsigned af[4][4], bf[8][2];
#pragma unroll
            for (int mt = 0; mt < 4; mt++) {
                int rb = wid * 64 + mt * 16 + g;
                af[mt][0] = as[rb * 20 + k0];
                af[mt][1] = as[(rb + 8) * 20 + k0];
                af[mt][2] = as[rb * 20 + k0 + 4];
                af[mt][3] = as[(rb + 8) * 20 + k0 + 4];
            }
#pragma unroll
            for (int nt = 0; nt < 8; nt++) {
                int nb = nt * 8 + g;
                bf[nt][0] = bs[nb * 20 + k0];
                bf[nt][1] = bs[nb * 20 + k0 + 4];
            }
#pragma unroll
            for (int mt = 0; mt < 4; mt++)
#pragma unroll
                for (int nt = 0; nt < 8; nt++) {
                    asm volatile(
                        "mma.sync.aligned.m16n8k16.row.col.f32.f16.f16.f32 "
                        "{%0,%1,%2,%3}, {%4,%5,%6,%7}, {%8,%9}, {%0,%1,%2,%3};\n"
                        : "+f"(acc[mt][nt][0]), "+f"(acc[mt][nt][1]),
                          "+f"(acc[mt][nt][2]), "+f"(acc[mt][nt][3])
                        : "r"(af[mt][0]), "r"(af[mt][1]), "r"(af[mt][2]), "r"(af[mt][3]),
                          "r"(bf[nt][0]), "r"(bf[nt][1]));
                }
        }
        __syncthreads();
        if (c + 3 < NCH) issue(c + 3);
    }

#pragma unroll
    for (int mt = 0; mt < 4; mt++)
#pragma unroll
        for (int rr = 0; rr < 2; rr++) {
            int m = bm + wid * 64 + mt * 16 + g + rr * 8;
            if (MODE == 0) {
                int win = m / 49, tok = m % 49;
#pragma unroll
                for (int nt = 0; nt < 8; nt++) {
                    int c0 = nt * 8 + tg * 2;
                    int n = bn + c0;
                    int part = n / 192, rem = n % 192, head = rem >> 5, dd = rem & 31;
                    size_t dst = ((size_t)(win * 6 + head) * 49 + tok) * 32 + dd;
                    float v0 = acc[mt][nt][rr * 2] + bias[n];
                    float v1 = acc[mt][nt][rr * 2 + 1] + bias[n + 1];
                    if (part == 0)      *(float2*)(g_q + dst) = make_float2(v0 * SCALE, v1 * SCALE);
                    else if (part == 1) *(float2*)(g_k + dst) = make_float2(v0, v1);
                    else                *(float2*)(g_v + dst) = make_float2(v0, v1);
                }
            } else if (MODE == 1) {
                int win = m / 49, tok = m % 49;
                int bb = win >> 6, w64 = win & 63, wh = w64 >> 3, wwi = w64 & 7;
                int ii = tok / 7, jj = tok % 7;
                int hh = wh * 7 + ii, gc = wwi * 7 + jj;
                if (shift) { hh = (hh + 7) % 56; gc = (gc + 7) % 56; }
                size_t rowo = ((size_t)bb * 3136 + hh * 56 + gc) * 192 + bn;
                const float* resp = (xin ? xin : (const float*)g_x) + rowo;
#pragma unroll
                for (int nt = 0; nt < 8; nt++) {
                    int c0 = nt * 8 + tg * 2;
                    float2 rv = *(const float2*)(resp + c0);
                    float2 bv = *(const float2*)(bias + bn + c0);
                    float v0 = acc[mt][nt][rr * 2] + bv.x + rv.x;
                    float v1 = acc[mt][nt][rr * 2 + 1] + bv.y + rv.y;
                    *(float2*)(g_x + rowo + c0) = make_float2(v0, v1);
                }
            } else if (MODE == 2) {
                __half* hrow = g_hid + (size_t)m * 768 + bn;
#pragma unroll
                for (int nt = 0; nt < 8; nt++) {
                    int c0 = nt * 8 + tg * 2;
                    float2 bv = *(const float2*)(bias + bn + c0);
                    float v0 = acc[mt][nt][rr * 2] + bv.x;
                    float v1 = acc[mt][nt][rr * 2 + 1] + bv.y;
                    v0 = v0 * 0.5f * (1.f + erff(v0 * 0.70710678118654752f));
                    v1 = v1 * 0.5f * (1.f + erff(v1 * 0.70710678118654752f));
                    *(__half2*)(hrow + c0) = __floats2half2_rn(v0, v1);
                }
            } else {
                size_t rowo = (size_t)m * 192 + bn;
                float* dst = outp ? outp : g_x;
#pragma unroll
                for (int nt = 0; nt < 8; nt++) {
                    int c0 = nt * 8 + tg * 2;
                    float2 rv = *(const float2*)(g_x + rowo + c0);
                    float2 bv = *(const float2*)(bias + bn + c0);
                    float v0 = acc[mt][nt][rr * 2] + bv.x + rv.x;
                    float v1 = acc[mt][nt][rr * 2 + 1] + bv.y + rv.y;
                    *(float2*)(dst + rowo + c0) = make_float2(v0, v1);
                }
            }
        }
}

extern "C" void kernel_launch(void* const* d_in, const int* in_sizes, int n_in,
                              void* d_out, int out_size) {
    const float* x     = (const float*)d_in[0];
    const float* n1w   = (const float*)d_in[1];
    const float* n1b   = (const float*)d_in[2];
    const float* qkvw  = (const float*)d_in[3];
    const float* qkvb  = (const float*)d_in[4];
    const float* rpb   = (const float*)d_in[5];
    const float* projw = (const float*)d_in[6];
    const float* projb = (const float*)d_in[7];
    const float* n2w   = (const float*)d_in[8];
    const float* n2b   = (const float*)d_in[9];
    const float* f1w   = (const float*)d_in[10];
    const float* f1b   = (const float*)d_in[11];
    const float* f2w   = (const float*)d_in[12];
    const float* f2b   = (const float*)d_in[13];

    cudaFuncSetAttribute(gemm_tc<0>, cudaFuncAttributeMaxDynamicSharedMemorySize, GT_DSMEM);
    cudaFuncSetAttribute(gemm_tc<1>, cudaFuncAttributeMaxDynamicSharedMemorySize, GT_DSMEM);
    cudaFuncSetAttribute(gemm_tc<2>, cudaFuncAttributeMaxDynamicSharedMemorySize, GT_DSMEM);
    cudaFuncSetAttribute(gemm_tc<3>, cudaFuncAttributeMaxDynamicSharedMemorySize, GT_DSMEM);

    __half* wq = nullptr; cudaGetSymbolAddress((void**)&wq, g_wcv);
    __half* wp = wq + 221184;
    __half* w1 = wq + 294912;
    __half* w2 = wq + 589824;
    convw_kernel<<<216, 256>>>(qkvw,  wq, 55296);
    convw_kernel<<<72,  256>>>(projw, wp, 18432);
    convw_kernel<<<288, 256>>>(f1w,   w1, 73728);
    convw_kernel<<<288, 256>>>(f2w,   w2, 73728);

    for (int d = 0; d < 2; d++) {
        int shift = d ? 3 : 0;
        const float* xin = (d == 0) ? x : nullptr;
        float* outp = (d == 1) ? (float*)d_out : nullptr;
        ln1_part_kernel<<<12544, 256>>>(n1w + d * 192, n1b + d * 192, shift, xin);
        gemm_tc<0><<<dim3(392, 9), 128, GT_DSMEM>>>(wq + (size_t)d * 110592, qkvb + d * 576, 192, 0, nullptr, nullptr);
        attn_kernel<<<12288, 256>>>(rpb + d * 169 * 6, shift);
        gemm_tc<1><<<dim3(392, 3), 128, GT_DSMEM>>>(wp + (size_t)d * 36864, projb + d * 192, 192, shift, xin, nullptr);
        ln2_kernel<<<12544, 256>>>(n2w + d * 192, n2b + d * 192);
        gemm_tc<2><<<dim3(392, 12), 128, GT_DSMEM>>>(w1 + (size_t)d * 147456, f1b + d * 768, 192, 0, nullptr, nullptr);
        gemm_tc<3><<<dim3(392, 3), 128, GT_DSMEM>>>(w2 + (size_t)d * 147456, f2b + d * 192, 768, 0, nullptr, outp);
    }
}

// round 11
// speedup vs baseline: 4.1195x; 1.1947x over previous
#include <cuda_runtime.h>
#include <cuda_fp16.h>
#include <math.h>
#include <stdint.h>

#define TOK 100352
#define SCALE 0.17677669529663687f

__device__ float  g_x[19267584];        // fp32 residual stream
__device__ __half g_hwin[19267584];
__device__ __half g_q[19267584];
__device__ __half g_k[19267584];
__device__ __half g_v[19267584];
__device__ __half g_attnout[19267584];
__device__ __half g_ln2[19267584];
__device__ __half g_hid[77070336];
__device__ __half g_wcv[884736];        // fp16 weights: qkv|proj|f1|f2 (both layers)

__device__ __forceinline__ float warp_sum(float v) {
#pragma unroll
    for (int o = 16; o; o >>= 1) v += __shfl_xor_sync(0xffffffffu, v, o);
    return v;
}
__device__ __forceinline__ uint32_t smem_u32(const void* p) {
    uint32_t a;
    asm("{ .reg .u64 t; cvta.to.shared.u64 t, %1; cvt.u32.u64 %0, t; }" : "=r"(a) : "l"(p));
    return a;
}
__device__ __forceinline__ void cpa16(uint32_t dst, const void* src) {
    asm volatile("cp.async.cg.shared.global [%0], [%1], 16;" :: "r"(dst), "l"(src));
}
__device__ __forceinline__ void mma16816(float* c, uint32_t a0, uint32_t a1, uint32_t a2, uint32_t a3,
                                         uint32_t b0, uint32_t b1) {
    asm volatile(
        "mma.sync.aligned.m16n8k16.row.col.f32.f16.f16.f32 "
        "{%0,%1,%2,%3}, {%4,%5,%6,%7}, {%8,%9}, {%0,%1,%2,%3};\n"
        : "+f"(c[0]), "+f"(c[1]), "+f"(c[2]), "+f"(c[3])
        : "r"(a0), "r"(a1), "r"(a2), "r"(a3), "r"(b0), "r"(b1));
}

// ---------------- weight pre-convert (fp32 -> fp16) ----------------
__global__ void convw_kernel(const float* __restrict__ s, __half* __restrict__ d, int n4) {
    int i = blockIdx.x * blockDim.x + threadIdx.x;
    if (i >= n4) return;
    float4 v = ((const float4*)s)[i];
    __half2* dp = (__half2*)d + i * 2;
    dp[0] = __floats2half2_rn(v.x, v.y);
    dp[1] = __floats2half2_rn(v.z, v.w);
}

// ---------------- LN kernels (fp16 outputs) ----------------
__global__ void ln1_part_kernel(const float* __restrict__ w, const float* __restrict__ b,
                                int shift, const float* __restrict__ xin) {
    int gw = (blockIdx.x * blockDim.x + threadIdx.x) >> 5;
    int lane = threadIdx.x & 31;
    if (gw >= TOK) return;
    int win = gw / 49, tok = gw % 49;
    int bb = win >> 6, w64 = win & 63;
    int wh = w64 >> 3, wwi = w64 & 7;
    int ii = tok / 7, jj = tok % 7;
    int sh = (wh * 7 + ii + shift) % 56;
    int sw = (wwi * 7 + jj + shift) % 56;
    const float* base = xin ? xin : g_x;
    const float* src = base + ((size_t)bb * 3136 + sh * 56 + sw) * 192;
    float v[6];
    float s = 0.f;
#pragma unroll
    for (int q = 0; q < 6; q++) { v[q] = src[lane + q * 32]; s += v[q]; }
    s = warp_sum(s);
    float mean = s * (1.f / 192.f);
    float ss = 0.f;
#pragma unroll
    for (int q = 0; q < 6; q++) { float d = v[q] - mean; ss += d * d; }
    ss = warp_sum(ss);
    float rstd = rsqrtf(ss * (1.f / 192.f) + 1e-5f);
    __half* dst = g_hwin + (size_t)gw * 192;
#pragma unroll
    for (int q = 0; q < 6; q++) {
        int c = lane + q * 32;
        dst[c] = __float2half((v[q] - mean) * rstd * w[c] + b[c]);
    }
}

__global__ void ln2_kernel(const float* __restrict__ w, const float* __restrict__ b) {
    int gw = (blockIdx.x * blockDim.x + threadIdx.x) >> 5;
    int lane = threadIdx.x & 31;
    if (gw >= TOK) return;
    const float* src = g_x + (size_t)gw * 192;
    float v[6];
    float s = 0.f;
#pragma unroll
    for (int q = 0; q < 6; q++) { v[q] = src[lane + q * 32]; s += v[q]; }
    s = warp_sum(s);
    float mean = s * (1.f / 192.f);
    float ss = 0.f;
#pragma unroll
    for (int q = 0; q < 6; q++) { float d = v[q] - mean; ss += d * d; }
    ss = warp_sum(ss);
    float rstd = rsqrtf(ss * (1.f / 192.f) + 1e-5f);
    __half* dst = g_ln2 + (size_t)gw * 192;
#pragma unroll
    for (int q = 0; q < 6; q++) {
        int c = lane + q * 32;
        dst[c] = __float2half((v[q] - mean) * rstd * w[c] + b[c]);
    }
}

__device__ __forceinline__ int reg3(int h) { return h < 49 ? 0 : (h < 53 ? 1 : 2); }

// ---------------- tensor-core attention: one (window, head) per 128-thread CTA ----------------
__global__ void __launch_bounds__(128) attn_kernel(const float* __restrict__ rpb, int shift) {
    __shared__ __half q_sm[64 * 72];
    __shared__ __half k_sm[56 * 72];
    __shared__ __half vt_sm[32 * 72];
    __shared__ __half p_sm[64 * 72];
    __shared__ float bias_sm[169];
    int bid = blockIdx.x;
    int win = bid / 6, head = bid % 6;
    int tid = threadIdx.x;
    const __half* qg = g_q + (size_t)bid * 1568;
    const __half* kg = g_k + (size_t)bid * 1568;
    const __half* vg = g_v + (size_t)bid * 1568;

    // phase 1: zero P, Vt, and q padding rows (padding correctness)
    for (int i2 = tid; i2 < 64 * 36; i2 += 128) ((uint32_t*)p_sm)[i2] = 0;
    for (int i2 = tid; i2 < 32 * 36; i2 += 128) ((uint32_t*)vt_sm)[i2] = 0;
    for (int i2 = 49 * 36 + tid; i2 < 64 * 36; i2 += 128) ((uint32_t*)q_sm)[i2] = 0;
    __syncthreads();

    // phase 2: fill q, k (vectorized), v transposed, bias table
    for (int idx = tid; idx < 392; idx += 128) {
        int row = idx >> 3, d0 = (idx & 7) * 4;
        *(uint2*)&q_sm[row * 72 + d0] = *(const uint2*)&qg[idx * 4];
        *(uint2*)&k_sm[row * 72 + d0] = *(const uint2*)&kg[idx * 4];
    }
    for (int idx = tid; idx < 1568; idx += 128) {
        int j = idx >> 5, d = idx & 31;
        vt_sm[d * 72 + j] = vg[idx];
    }
    for (int idx = tid; idx < 169; idx += 128) bias_sm[idx] = rpb[idx * 6 + head];
    __syncthreads();

    const int wid = tid >> 5, lane = tid & 31;
    const int g = lane >> 2, tg = lane & 3;
    const int i0 = 16 * wid + g, i1 = i0 + 8;

    // S = q @ k^T : 7 n8-tiles, 2 k16-steps
    float c[7][4];
#pragma unroll
    for (int t = 0; t < 7; t++) { c[t][0] = c[t][1] = c[t][2] = c[t][3] = 0.f; }
#pragma unroll
    for (int s = 0; s < 2; s++) {
        uint32_t a0 = *(uint32_t*)&q_sm[i0 * 72 + 2 * tg + 16 * s];
        uint32_t a1 = *(uint32_t*)&q_sm[i1 * 72 + 2 * tg + 16 * s];
        uint32_t a2 = *(uint32_t*)&q_sm[i0 * 72 + 2 * tg + 8 + 16 * s];
        uint32_t a3 = *(uint32_t*)&q_sm[i1 * 72 + 2 * tg + 8 + 16 * s];
#pragma unroll
        for (int t = 0; t < 7; t++) {
            uint32_t b0 = *(uint32_t*)&k_sm[(8 * t + g) * 72 + 2 * tg + 16 * s];
            uint32_t b1 = *(uint32_t*)&k_sm[(8 * t + g) * 72 + 2 * tg + 8 + 16 * s];
            mma16816(c[t], a0, a1, a2, a3, b0, b1);
        }
    }

    // bias + mask + softmax (rows i0 and i1, cols j = 8t + 2tg + {0,1})
    int w64 = win & 63, wh = w64 >> 3, wwi = w64 & 7;
    int ic0 = i0 < 49 ? i0 : 48, ic1 = i1 < 49 ? i1 : 48;
    int yi0 = ic0 / 7, xi0 = ic0 % 7, yi1 = ic1 / 7, xi1 = ic1 % 7;
    int ri0 = 0, ri1 = 0;
    if (shift) {
        ri0 = reg3(wh * 7 + yi0) * 3 + reg3(wwi * 7 + xi0);
        ri1 = reg3(wh * 7 + yi1) * 3 + reg3(wwi * 7 + xi1);
    }
    float v0[7][2], v1[7][2];
#pragma unroll
    for (int t = 0; t < 7; t++) {
#pragma unroll
        for (int e = 0; e < 2; e++) {
            int j = 8 * t + 2 * tg + e;
            bool valid = j < 49;
            int jc = valid ? j : 0;
            int yj = jc / 7, xj = jc % 7;
            float m0 = 0.f, m1 = 0.f;
            if (shift) {
                int rj = reg3(wh * 7 + yj) * 3 + reg3(wwi * 7 + xj);
                if (ri0 != rj) m0 = -100.f;
                if (ri1 != rj) m1 = -100.f;
            }
            float b0 = bias_sm[(yi0 - yj + 6) * 13 + (xi0 - xj + 6)];
            float b1 = bias_sm[(yi1 - yj + 6) * 13 + (xi1 - xj + 6)];
            v0[t][e] = valid ? c[t][e] + b0 + m0 : -1e9f;
            v1[t][e] = valid ? c[t][2 + e] + b1 + m1 : -1e9f;
        }
    }
    float mx0 = -1e30f, mx1 = -1e30f;
#pragma unroll
    for (int t = 0; t < 7; t++) {
        mx0 = fmaxf(mx0, fmaxf(v0[t][0], v0[t][1]));
        mx1 = fmaxf(mx1, fmaxf(v1[t][0], v1[t][1]));
    }
    mx0 = fmaxf(mx0, __shfl_xor_sync(0xffffffffu, mx0, 1));
    mx0 = fmaxf(mx0, __shfl_xor_sync(0xffffffffu, mx0, 2));
    mx1 = fmaxf(mx1, __shfl_xor_sync(0xffffffffu, mx1, 1));
    mx1 = fmaxf(mx1, __shfl_xor_sync(0xffffffffu, mx1, 2));
    float sm0 = 0.f, sm1 = 0.f;
#pragma unroll
    for (int t = 0; t < 7; t++) {
#pragma unroll
        for (int e = 0; e < 2; e++) {
            v0[t][e] = __expf(v0[t][e] - mx0); sm0 += v0[t][e];
            v1[t][e] = __expf(v1[t][e] - mx1); sm1 += v1[t][e];
        }
    }
    sm0 += __shfl_xor_sync(0xffffffffu, sm0, 1);
    sm0 += __shfl_xor_sync(0xffffffffu, sm0, 2);
    sm1 += __shfl_xor_sync(0xffffffffu, sm1, 1);
    sm1 += __shfl_xor_sync(0xffffffffu, sm1, 2);
    float inv0 = 1.f / sm0, inv1 = 1.f / sm1;
#pragma unroll
    for (int t = 0; t < 7; t++) {
        *(__half2*)&p_sm[i0 * 72 + 8 * t + 2 * tg] = __floats2half2_rn(v0[t][0] * inv0, v0[t][1] * inv0);
        *(__half2*)&p_sm[i1 * 72 + 8 * t + 2 * tg] = __floats2half2_rn(v1[t][0] * inv1, v1[t][1] * inv1);
    }
    __syncthreads();

    // O = P @ V : 4 n8-tiles (d), 4 k16-steps (j)
    float o[4][4];
#pragma unroll
    for (int t = 0; t < 4; t++) { o[t][0] = o[t][1] = o[t][2] = o[t][3] = 0.f; }
#pragma unroll
    for (int s = 0; s < 4; s++) {
        uint32_t a0 = *(uint32_t*)&p_sm[i0 * 72 + 2 * tg + 16 * s];
        uint32_t a1 = *(uint32_t*)&p_sm[i1 * 72 + 2 * tg + 16 * s];
        uint32_t a2 = *(uint32_t*)&p_sm[i0 * 72 + 2 * tg + 8 + 16 * s];
        uint32_t a3 = *(uint32_t*)&p_sm[i1 * 72 + 2 * tg + 8 + 16 * s];
#pragma unroll
        for (int t = 0; t < 4; t++) {
            uint32_t b0 = *(uint32_t*)&vt_sm[(8 * t + g) * 72 + 2 * tg + 16 * s];
            uint32_t b1 = *(uint32_t*)&vt_sm[(8 * t + g) * 72 + 2 * tg + 8 + 16 * s];
            mma16816(o[t], a0, a1, a2, a3, b0, b1);
        }
    }
    if (i0 < 49) {
        __half* dst = g_attnout + ((size_t)(win * 49 + i0)) * 192 + head * 32;
#pragma unroll
        for (int t = 0; t < 4; t++)
            *(__half2*)&dst[8 * t + 2 * tg] = __floats2half2_rn(o[t][0], o[t][1]);
    }
    if (i1 < 49) {
        __half* dst = g_attnout + ((size_t)(win * 49 + i1)) * 192 + head * 32;
#pragma unroll
        for (int t = 0; t < 4; t++)
            *(__half2*)&dst[8 * t + 2 * tg] = __floats2half2_rn(o[t][2], o[t][3]);
    }
}

// -------- fp16 mma.sync GEMM: CTA 256x64, 128 threads, warp tile 64x64, 3-stage cp.async --------
#define GT_DSMEM 76800

template <int MODE>
__global__ void __launch_bounds__(128) gemm_tc(const __half* __restrict__ Wt,
                                               const float* __restrict__ bias,
                                               int K, int shift,
                                               const float* __restrict__ xin,
                                               float* __restrict__ outp) {
    extern __shared__ unsigned sm[];
    const __half* A = (MODE == 0) ? g_hwin : (MODE == 1) ? g_attnout : (MODE == 2) ? g_ln2 : g_hid;
    const int bm = blockIdx.x * 256;
    const int bn = blockIdx.y * 64;
    const int tid = threadIdx.x, wid = tid >> 5, lane = tid & 31;
    const int g = lane >> 2, tg = lane & 3;
    const uint32_t sbase = smem_u32(sm);
    const __half* Abase = A + (size_t)bm * K;
    const __half* Bbase = Wt + (size_t)bn * K;
    const int NCH = K >> 5;

    float acc[4][8][4];
#pragma unroll
    for (int i = 0; i < 4; i++)
#pragma unroll
        for (int j = 0; j < 8; j++)
#pragma unroll
            for (int r = 0; r < 4; r++) acc[i][j][r] = 0.f;

    auto issue = [&](int c) {
        uint32_t sb = sbase + (c % 3) * 25600;
        const __half* Ab = Abase + c * 32;
#pragma unroll
        for (int i = 0; i < 8; i++) {
            int f8 = tid + i * 128, row = f8 >> 2, ch = f8 & 3;
            cpa16(sb + (row * 20 + ch * 4) * 4, Ab + (size_t)row * K + ch * 8);
        }
        const __half* Bb = Bbase + c * 32;
#pragma unroll
        for (int i = 0; i < 2; i++) {
            int f8 = tid + i * 128, row = f8 >> 2, ch = f8 & 3;
            cpa16(sb + 20480 + (row * 20 + ch * 4) * 4, Bb + (size_t)row * K + ch * 8);
        }
        asm volatile("cp.async.commit_group;" ::: "memory");
    };

    issue(0);
    if (NCH > 1) issue(1);
    if (NCH > 2) issue(2);

    for (int c = 0; c < NCH; c++) {
        if (c + 2 < NCH)      asm volatile("cp.async.wait_group 2;" ::: "memory");
        else if (c + 1 < NCH) asm volatile("cp.async.wait_group 1;" ::: "memory");
        else                  asm volatile("cp.async.wait_group 0;" ::: "memory");
        __syncthreads();
        const unsigned* as = sm + (c % 3) * 6400;
        const unsigned* bs = as + 5120;
#pragma unroll
        for (int s = 0; s < 2; s++) {
            const int k0 = s * 8 + tg;
            unsigned af[4][4], bf[8][2];
#pragma unroll
            for (int mt = 0; mt < 4; mt++) {
                int rb = wid * 64 + mt * 16 + g;
                af[mt][0] = as[rb * 20 + k0];
                af[mt][1] = as[(rb + 8) * 20 + k0];
                af[mt][2] = as[rb * 20 + k0 + 4];
                af[mt][3] = as[(rb + 8) * 20 + k0 + 4];
            }
#pragma unroll
            for (int nt = 0; nt < 8; nt++) {
                int nb = nt * 8 + g;
                bf[nt][0] = bs[nb * 20 + k0];
                bf[nt][1] = bs[nb * 20 + k0 + 4];
            }
#pragma unroll
            for (int mt = 0; mt < 4; mt++)
#pragma unroll
                for (int nt = 0; nt < 8; nt++)
                    mma16816(acc[mt][nt], af[mt][0], af[mt][1], af[mt][2], af[mt][3],
                             bf[nt][0], bf[nt][1]);
        }
        __syncthreads();
        if (c + 3 < NCH) issue(c + 3);
    }

#pragma unroll
    for (int mt = 0; mt < 4; mt++)
#pragma unroll
        for (int rr = 0; rr < 2; rr++) {
            int m = bm + wid * 64 + mt * 16 + g + rr * 8;
            if (MODE == 0) {
                int win = m / 49, tok = m % 49;
#pragma unroll
                for (int nt = 0; nt < 8; nt++) {
                    int c0 = nt * 8 + tg * 2;
                    int n = bn + c0;
                    int part = n / 192, rem = n % 192, head = rem >> 5, dd = rem & 31;
                    size_t dst = ((size_t)(win * 6 + head) * 49 + tok) * 32 + dd;
                    float v0 = acc[mt][nt][rr * 2] + bias[n];
                    float v1 = acc[mt][nt][rr * 2 + 1] + bias[n + 1];
                    if (part == 0)      *(__half2*)(g_q + dst) = __floats2half2_rn(v0 * SCALE, v1 * SCALE);
                    else if (part == 1) *(__half2*)(g_k + dst) = __floats2half2_rn(v0, v1);
                    else                *(__half2*)(g_v + dst) = __floats2half2_rn(v0, v1);
                }
            } else if (MODE == 1) {
                int win = m / 49, tok = m % 49;
                int bb = win >> 6, w64 = win & 63, wh = w64 >> 3, wwi = w64 & 7;
                int ii = tok / 7, jj = tok % 7;
                int hh = wh * 7 + ii, gc = wwi * 7 + jj;
                if (shift) { hh = (hh + 7) % 56; gc = (gc + 7) % 56; }
                size_t rowo = ((size_t)bb * 3136 + hh * 56 + gc) * 192 + bn;
                const float* resp = (xin ? xin : (const float*)g_x) + rowo;
#pragma unroll
                for (int nt = 0; nt < 8; nt++) {
                    int c0 = nt * 8 + tg * 2;
                    float2 rv = *(const float2*)(resp + c0);
                    float2 bv = *(const float2*)(bias + bn + c0);
                    float v0 = acc[mt][nt][rr * 2] + bv.x + rv.x;
                    float v1 = acc[mt][nt][rr * 2 + 1] + bv.y + rv.y;
                    *(float2*)(g_x + rowo + c0) = make_float2(v0, v1);
                }
            } else if (MODE == 2) {
                __half* hrow = g_hid + (size_t)m * 768 + bn;
#pragma unroll
                for (int nt = 0; nt < 8; nt++) {
                    int c0 = nt * 8 + tg * 2;
                    float2 bv = *(const float2*)(bias + bn + c0);
                    float v0 = acc[mt][nt][rr * 2] + bv.x;
                    float v1 = acc[mt][nt][rr * 2 + 1] + bv.y;
                    v0 = v0 * 0.5f * (1.f + erff(v0 * 0.70710678118654752f));
                    v1 = v1 * 0.5f * (1.f + erff(v1 * 0.70710678118654752f));
                    *(__half2*)(hrow + c0) = __floats2half2_rn(v0, v1);
                }
            } else {
                size_t rowo = (size_t)m * 192 + bn;
                float* dst = outp ? outp : g_x;
#pragma unroll
                for (int nt = 0; nt < 8; nt++) {
                    int c0 = nt * 8 + tg * 2;
                    float2 rv = *(const float2*)(g_x + rowo + c0);
                    float2 bv = *(const float2*)(bias + bn + c0);
                    float v0 = acc[mt][nt][rr * 2] + bv.x + rv.x;
                    float v1 = acc[mt][nt][rr * 2 + 1] + bv.y + rv.y;
                    *(float2*)(dst + rowo + c0) = make_float2(v0, v1);
                }
            }
        }
}

extern "C" void kernel_launch(void* const* d_in, const int* in_sizes, int n_in,
                              void* d_out, int out_size) {
    const float* x     = (const float*)d_in[0];
    const float* n1w   = (const float*)d_in[1];
    const float* n1b   = (const float*)d_in[2];
    const float* qkvw  = (const float*)d_in[3];
    const float* qkvb  = (const float*)d_in[4];
    const float* rpb   = (const float*)d_in[5];
    const float* projw = (const float*)d_in[6];
    const float* projb = (const float*)d_in[7];
    const float* n2w   = (const float*)d_in[8];
    const float* n2b   = (const float*)d_in[9];
    const float* f1w   = (const float*)d_in[10];
    const float* f1b   = (const float*)d_in[11];
    const float* f2w   = (const float*)d_in[12];
    const float* f2b   = (const float*)d_in[13];

    cudaFuncSetAttribute(gemm_tc<0>, cudaFuncAttributeMaxDynamicSharedMemorySize, GT_DSMEM);
    cudaFuncSetAttribute(gemm_tc<1>, cudaFuncAttributeMaxDynamicSharedMemorySize, GT_DSMEM);
    cudaFuncSetAttribute(gemm_tc<2>, cudaFuncAttributeMaxDynamicSharedMemorySize, GT_DSMEM);
    cudaFuncSetAttribute(gemm_tc<3>, cudaFuncAttributeMaxDynamicSharedMemorySize, GT_DSMEM);

    __half* wq = nullptr; cudaGetSymbolAddress((void**)&wq, g_wcv);
    __half* wp = wq + 221184;
    __half* w1 = wq + 294912;
    __half* w2 = wq + 589824;
    convw_kernel<<<216, 256>>>(qkvw,  wq, 55296);
    convw_kernel<<<72,  256>>>(projw, wp, 18432);
    convw_kernel<<<288, 256>>>(f1w,   w1, 73728);
    convw_kernel<<<288, 256>>>(f2w,   w2, 73728);

    for (int d = 0; d < 2; d++) {
        int shift = d ? 3 : 0;
        const float* xin = (d == 0) ? x : nullptr;
        float* outp = (d == 1) ? (float*)d_out : nullptr;
        ln1_part_kernel<<<12544, 256>>>(n1w + d * 192, n1b + d * 192, shift, xin);
        gemm_tc<0><<<dim3(392, 9), 128, GT_DSMEM>>>(wq + (size_t)d * 110592, qkvb + d * 576, 192, 0, nullptr, nullptr);
        attn_kernel<<<12288, 128>>>(rpb + d * 169 * 6, shift);
        gemm_tc<1><<<dim3(392, 3), 128, GT_DSMEM>>>(wp + (size_t)d * 36864, projb + d * 192, 192, shift, xin, nullptr);
        ln2_kernel<<<12544, 256>>>(n2w + d * 192, n2b + d * 192);
        gemm_tc<2><<<dim3(392, 12), 128, GT_DSMEM>>>(w1 + (size_t)d * 147456, f1b + d * 768, 192, 0, nullptr, nullptr);
        gemm_tc<3><<<dim3(392, 3), 128, GT_DSMEM>>>(w2 + (size_t)d * 147456, f2b + d * 192, 768, 0, nullptr, outp);
    }
}